// round 2
// baseline (speedup 1.0000x reference)
#include <cuda_runtime.h>
#include <math.h>

// Problem constants
#define BB   16
#define NQ   2304
#define DD   512
#define NH   8
#define DK   64
#define NKK  256
#define HHH  48
#define OHH  16

// Scratch (device globals; allocation-free per harness rules)
__device__ float g_qp[BB * NQ * DD];     // Q projection
__device__ float g_x [BB * NKK * DD];    // conv+LN output
__device__ float g_kp[BB * NKK * DD];    // K projection
__device__ float g_vp[BB * NKK * DD];    // V projection
__device__ float g_ou[BB * NQ * DD];     // unnormalized attention output
__device__ float g_vs[BB * DD];          // column sums of V per batch
__device__ float g_ssq[BB * NH];         // sum of p^2 per (b,h)
__device__ float g_is [BB * NH];         // 1/sqrt(var+eps) per (b,h)

// ---------------------------------------------------------------------------
// Generic tiled fp32 GEMM: C = A(MxK) @ B(KxN) + bias(N)
// 128x128 tile, BK=8, 256 threads, 8x8 per thread.
// ---------------------------------------------------------------------------
__global__ __launch_bounds__(256) void gemm_bias(
    const float* __restrict__ A, const float* __restrict__ Bm,
    const float* __restrict__ bias, float* __restrict__ C,
    int M, int N, int K)
{
    __shared__ float Ast[8][132];   // transposed A tile, padded
    __shared__ float Bs[8][128];

    const int tid = threadIdx.x;
    const int tx = tid & 15, ty = tid >> 4;
    const int row0 = blockIdx.y * 128;
    const int col0 = blockIdx.x * 128;

    const int ar  = tid >> 1;          // 0..127
    const int ac4 = (tid & 1) * 4;     // 0 or 4
    const int br  = tid >> 5;          // 0..7
    const int bc4 = (tid & 31) * 4;    // 0..124

    float acc[8][8];
#pragma unroll
    for (int i = 0; i < 8; i++)
#pragma unroll
        for (int j = 0; j < 8; j++) acc[i][j] = 0.f;

    for (int k0 = 0; k0 < K; k0 += 8) {
        float4 av = *(const float4*)&A[(size_t)(row0 + ar) * K + k0 + ac4];
        float4 bv = *(const float4*)&Bm[(size_t)(k0 + br) * N + col0 + bc4];
        __syncthreads();
        Ast[ac4 + 0][ar] = av.x;
        Ast[ac4 + 1][ar] = av.y;
        Ast[ac4 + 2][ar] = av.z;
        Ast[ac4 + 3][ar] = av.w;
        *(float4*)&Bs[br][bc4] = bv;
        __syncthreads();
#pragma unroll
        for (int kk = 0; kk < 8; kk++) {
            float4 a0 = *(const float4*)&Ast[kk][ty * 8];
            float4 a1 = *(const float4*)&Ast[kk][ty * 8 + 4];
            float4 b0 = *(const float4*)&Bs[kk][tx * 8];
            float4 b1 = *(const float4*)&Bs[kk][tx * 8 + 4];
            float ra[8] = {a0.x, a0.y, a0.z, a0.w, a1.x, a1.y, a1.z, a1.w};
            float rb[8] = {b0.x, b0.y, b0.z, b0.w, b1.x, b1.y, b1.z, b1.w};
#pragma unroll
            for (int i = 0; i < 8; i++)
#pragma unroll
                for (int j = 0; j < 8; j++)
                    acc[i][j] += ra[i] * rb[j];
        }
    }

    float4 bz0 = *(const float4*)&bias[col0 + tx * 8];
    float4 bz1 = *(const float4*)&bias[col0 + tx * 8 + 4];
    float rb[8] = {bz0.x, bz0.y, bz0.z, bz0.w, bz1.x, bz1.y, bz1.z, bz1.w};
#pragma unroll
    for (int i = 0; i < 8; i++) {
        int gr = row0 + ty * 8 + i;
        float4 c0 = make_float4(acc[i][0] + rb[0], acc[i][1] + rb[1],
                                acc[i][2] + rb[2], acc[i][3] + rb[3]);
        float4 c1 = make_float4(acc[i][4] + rb[4], acc[i][5] + rb[5],
                                acc[i][6] + rb[6], acc[i][7] + rb[7]);
        *(float4*)&C[(size_t)gr * N + col0 + tx * 8]     = c0;
        *(float4*)&C[(size_t)gr * N + col0 + tx * 8 + 4] = c1;
    }
}

// ---------------------------------------------------------------------------
// Depthwise 4x4 stride-3 conv (pad 1) + LayerNorm over channels.
// One block per (b, output pixel); 256 threads, 2 channels each.
// ---------------------------------------------------------------------------
__global__ __launch_bounds__(256) void convln_kernel(
    const float* __restrict__ q, const float* __restrict__ srw,
    const float* __restrict__ srb, const float* __restrict__ lng,
    const float* __restrict__ lnb)
{
    const int b  = blockIdx.y;
    const int op = blockIdx.x;            // 0..255
    const int oh = op >> 4, ow = op & 15;
    const int tid = threadIdx.x;
    const int c0 = tid, c1 = tid + 256;

    float a0 = srb[c0], a1 = srb[c1];
#pragma unroll
    for (int kh = 0; kh < 4; kh++) {
        int ih = oh * 3 - 1 + kh;
        if (ih < 0 || ih >= HHH) continue;
#pragma unroll
        for (int kw = 0; kw < 4; kw++) {
            int iw = ow * 3 - 1 + kw;
            if (iw < 0 || iw >= HHH) continue;
            const float* qr = q + ((size_t)b * NQ + ih * HHH + iw) * DD;
            a0 += srw[c0 * 16 + kh * 4 + kw] * qr[c0];
            a1 += srw[c1 * 16 + kh * 4 + kw] * qr[c1];
        }
    }

    float s  = a0 + a1;
    float s2 = a0 * a0 + a1 * a1;
#pragma unroll
    for (int off = 16; off; off >>= 1) {
        s  += __shfl_xor_sync(0xFFFFFFFFu, s,  off);
        s2 += __shfl_xor_sync(0xFFFFFFFFu, s2, off);
    }
    __shared__ float rs[8], rs2[8];
    if ((tid & 31) == 0) { rs[tid >> 5] = s; rs2[tid >> 5] = s2; }
    __syncthreads();
    if (tid == 0) {
        float ts = 0.f, ts2 = 0.f;
#pragma unroll
        for (int i = 0; i < 8; i++) { ts += rs[i]; ts2 += rs2[i]; }
        rs[0] = ts; rs2[0] = ts2;
    }
    __syncthreads();
    const float mu   = rs[0] * (1.f / 512.f);
    const float var  = rs2[0] * (1.f / 512.f) - mu * mu;
    const float rstd = rsqrtf(var + 1e-5f);

    float* xo = g_x + ((size_t)b * NKK + op) * DD;
    xo[c0] = (a0 - mu) * rstd * lng[c0] + lnb[c0];
    xo[c1] = (a1 - mu) * rstd * lng[c1] + lnb[c1];
}

// ---------------------------------------------------------------------------
// V column sums per batch
// ---------------------------------------------------------------------------
__global__ void vcolsum_kernel()
{
    const int b = blockIdx.x;
    const int c = threadIdx.x;      // 512 threads
    float s = 0.f;
    for (int k = 0; k < NKK; k++)
        s += g_vp[((size_t)b * NKK + k) * DD + c];
    g_vs[b * DD + c] = s;
}

__global__ void zero_ssq_kernel()
{
    if (threadIdx.x < BB * NH) g_ssq[threadIdx.x] = 0.f;
}

__global__ void stats_kernel()
{
    const int i = threadIdx.x;
    if (i < BB * NH) {
        const float m = 1.f / 256.f;
        float va = g_ssq[i] / (2304.f * 256.f) - m * m;
        g_is[i] = rsqrtf(va + 1e-5f);
    }
}

// Elementwise: ou = (ou - m*vs[b,c]) * inv_s[b,h]
__global__ void norm_kernel()
{
    const float m = 1.f / 256.f;
    int idx = blockIdx.x * 256 + threadIdx.x;
    const int total = BB * NQ * DD;
    if (idx < total) {
        int c = idx & 511;
        int b = idx / (NQ * DD);
        int h = c >> 6;
        g_ou[idx] = (g_ou[idx] - m * g_vs[b * DD + c]) * g_is[b * NH + h];
    }
}

// ---------------------------------------------------------------------------
// Fused attention: per block = (b, 16-query tile).
// smem: scores [16 q][8 h][257], q tile [16][513], k/v chunk [16][513].
// QK -> head mix (tw,tb) -> softmax + sum(p^2) -> P@V
// ---------------------------------------------------------------------------
#define SC_STRIDE 257
#define RW 513
#define ATT_SMEM_FLOATS (16 * 8 * SC_STRIDE + 2 * 16 * RW + 64 + 8 + 8)

__global__ __launch_bounds__(256, 1) void attn_kernel(
    const float* __restrict__ tw, const float* __restrict__ tb)
{
    extern __shared__ float sm[];
    float* sc  = sm;                              // 16*8*257
    float* qs  = sc  + 16 * 8 * SC_STRIDE;        // 16*513
    float* ks  = qs  + 16 * RW;                   // 16*513 (reused for V)
    float* tws = ks  + 16 * RW;                   // 64
    float* tbs = tws + 64;                        // 8
    float* ssq = tbs + 8;                         // 8

    const int tid = threadIdx.x;
    const int b   = blockIdx.y;
    const int q0  = blockIdx.x * 16;

    if (tid < 64) tws[tid] = tw[tid];
    if (tid < 8) { tbs[tid] = tb[tid]; ssq[tid] = 0.f; }

    // load Q tile (16 x 512)
    {
        const float* qp = g_qp + ((size_t)b * NQ + q0) * DD;
        for (int idx = tid; idx < 2048; idx += 256) {
            int r  = idx >> 7;
            int c4 = (idx & 127) << 2;
            float4 v = *(const float4*)&qp[r * DD + c4];
            float* d = &qs[r * RW + c4];
            d[0] = v.x; d[1] = v.y; d[2] = v.z; d[3] = v.w;
        }
    }

    // ---- QK: scores for all 8 heads ----
    const int qq = tid >> 4;
    const int kl = tid & 15;
    for (int kc = 0; kc < 16; kc++) {
        __syncthreads();
        const float* kp = g_kp + ((size_t)b * NKK + kc * 16) * DD;
        for (int idx = tid; idx < 2048; idx += 256) {
            int r  = idx >> 7;
            int c4 = (idx & 127) << 2;
            float4 v = *(const float4*)&kp[r * DD + c4];
            float* d = &ks[r * RW + c4];
            d[0] = v.x; d[1] = v.y; d[2] = v.z; d[3] = v.w;
        }
        __syncthreads();
        const float* qrow = qs + qq * RW;
        const float* krow = ks + kl * RW;
        float acc[8];
#pragma unroll
        for (int h = 0; h < 8; h++) {
            float a = 0.f;
#pragma unroll
            for (int cc = 0; cc < 64; cc++)
                a += qrow[h * 64 + cc] * krow[h * 64 + cc];
            acc[h] = a;
        }
        const int k = kc * 16 + kl;
#pragma unroll
        for (int h = 0; h < 8; h++)
            sc[(qq * 8 + h) * SC_STRIDE + k] = acc[h] * 0.125f;
    }
    __syncthreads();

    // ---- head mixing: s2[o][k] = tb[o] + sum_i tw[o][i]*s[i][k] ----
    {
        const int k = tid;  // 0..255
        for (int q = 0; q < 16; q++) {
            float r[8];
#pragma unroll
            for (int i = 0; i < 8; i++) r[i] = sc[(q * 8 + i) * SC_STRIDE + k];
            float o_[8];
#pragma unroll
            for (int o = 0; o < 8; o++) {
                float s = tbs[o];
#pragma unroll
                for (int i = 0; i < 8; i++) s += tws[o * 8 + i] * r[i];
                o_[o] = s;
            }
#pragma unroll
            for (int o = 0; o < 8; o++) sc[(q * 8 + o) * SC_STRIDE + k] = o_[o];
        }
    }
    __syncthreads();

    // ---- softmax per (q,o) row + sum of squares ----
    if (tid < 128) {
        float* row = sc + tid * SC_STRIDE;
        float mx = -1e30f;
        for (int k = 0; k < 256; k++) mx = fmaxf(mx, row[k]);
        float s = 0.f;
        for (int k = 0; k < 256; k++) { float e = expf(row[k] - mx); row[k] = e; s += e; }
        float inv = 1.f / s;
        float lss = 0.f;
        for (int k = 0; k < 256; k++) { float p = row[k] * inv; row[k] = p; lss += p * p; }
        atomicAdd(&ssq[tid & 7], lss);
    }
    __syncthreads();
    if (tid < 8) atomicAdd(&g_ssq[b * NH + tid], ssq[tid]);

    // ---- P @ V ----
    const int qg = tid >> 6;    // 0..3 -> 4 q rows each
    const int cg = tid & 63;    // 0..63 -> 8 output cols each
    const int o  = cg >> 3;
    float acc2[4][8];
#pragma unroll
    for (int i = 0; i < 4; i++)
#pragma unroll
        for (int j = 0; j < 8; j++) acc2[i][j] = 0.f;

    for (int vc = 0; vc < 16; vc++) {
        __syncthreads();
        const float* vp = g_vp + ((size_t)b * NKK + vc * 16) * DD;
        for (int idx = tid; idx < 2048; idx += 256) {
            int r  = idx >> 7;
            int c4 = (idx & 127) << 2;
            float4 v = *(const float4*)&vp[r * DD + c4];
            float* d = &ks[r * RW + c4];
            d[0] = v.x; d[1] = v.y; d[2] = v.z; d[3] = v.w;
        }
        __syncthreads();
#pragma unroll
        for (int kl2 = 0; kl2 < 16; kl2++) {
            const int k = vc * 16 + kl2;
            float pv[8];
#pragma unroll
            for (int j = 0; j < 8; j++) pv[j] = ks[kl2 * RW + cg * 8 + j];
#pragma unroll
            for (int q4 = 0; q4 < 4; q4++) {
                float p = sc[((qg * 4 + q4) * 8 + o) * SC_STRIDE + k];
#pragma unroll
                for (int j = 0; j < 8; j++) acc2[q4][j] += p * pv[j];
            }
        }
    }

#pragma unroll
    for (int q4 = 0; q4 < 4; q4++) {
        float* outp = g_ou + ((size_t)b * NQ + q0 + qg * 4 + q4) * DD + cg * 8;
        float4 c0 = make_float4(acc2[q4][0], acc2[q4][1], acc2[q4][2], acc2[q4][3]);
        float4 c1 = make_float4(acc2[q4][4], acc2[q4][5], acc2[q4][6], acc2[q4][7]);
        *(float4*)&outp[0] = c0;
        *(float4*)&outp[4] = c1;
    }
}

// ---------------------------------------------------------------------------
extern "C" void kernel_launch(void* const* d_in, const int* in_sizes, int n_in,
                              void* d_out, int out_size)
{
    (void)in_sizes; (void)n_in; (void)out_size;
    const float* queries = (const float*)d_in[0];
    const float* Wq = (const float*)d_in[1];
    const float* bq = (const float*)d_in[2];
    const float* Wk = (const float*)d_in[3];
    const float* bk = (const float*)d_in[4];
    const float* Wv = (const float*)d_in[5];
    const float* bv = (const float*)d_in[6];
    const float* Wo = (const float*)d_in[7];
    const float* bo = (const float*)d_in[8];
    const float* srw = (const float*)d_in[9];
    const float* srb = (const float*)d_in[10];
    const float* lng = (const float*)d_in[11];
    const float* lnb = (const float*)d_in[12];
    const float* tw  = (const float*)d_in[13];
    const float* tb  = (const float*)d_in[14];
    float* out = (float*)d_out;

    float *qp, *x, *kp, *vp, *ou;
    cudaGetSymbolAddress((void**)&qp, g_qp);
    cudaGetSymbolAddress((void**)&x,  g_x);
    cudaGetSymbolAddress((void**)&kp, g_kp);
    cudaGetSymbolAddress((void**)&vp, g_vp);
    cudaGetSymbolAddress((void**)&ou, g_ou);

    const size_t attn_smem = ATT_SMEM_FLOATS * sizeof(float);
    cudaFuncSetAttribute(attn_kernel,
                         cudaFuncAttributeMaxDynamicSharedMemorySize,
                         (int)attn_smem);

    zero_ssq_kernel<<<1, 128>>>();

    // Q projection: (16*2304, 512) @ (512, 512)
    gemm_bias<<<dim3(4, 288), 256>>>(queries, Wq, bq, qp, BB * NQ, DD, DD);

    // spatial reduction conv + LN
    convln_kernel<<<dim3(256, 16), 256>>>(queries, srw, srb, lng, lnb);

    // K, V projections: (16*256, 512) @ (512, 512)
    gemm_bias<<<dim3(4, 32), 256>>>(x, Wk, bk, kp, BB * NKK, DD, DD);
    gemm_bias<<<dim3(4, 32), 256>>>(x, Wv, bv, vp, BB * NKK, DD, DD);

    vcolsum_kernel<<<BB, 512>>>();

    // fused attention
    attn_kernel<<<dim3(NQ / 16, BB), 256, attn_smem>>>(tw, tb);

    stats_kernel<<<1, 128>>>();

    // normalize (InstanceNorm folded into output)
    norm_kernel<<<(BB * NQ * DD + 255) / 256, 256>>>();

    // output projection -> d_out
    gemm_bias<<<dim3(4, 288), 256>>>(ou, Wo, bo, out, BB * NQ, DD, DD);
}

// round 4
// speedup vs baseline: 1.2093x; 1.2093x over previous
#include <cuda_runtime.h>
#include <math.h>
#include <cstdint>

// Problem constants
#define BB   16
#define NQ   2304
#define DD   512
#define NH   8
#define DK   64
#define NKK  256
#define HHH  48

// Scratch (device globals; allocation-free per harness rules)
__device__ float g_qp[BB * NQ * DD];     // Q projection
__device__ float g_x [BB * NKK * DD];    // conv+LN output
__device__ float g_kp[BB * NKK * DD];    // K projection
__device__ float g_vp[BB * NKK * DD];    // V projection
__device__ float g_ou[BB * NQ * DD];     // unnormalized attention output
__device__ float g_vs[BB * DD];          // column sums of V per batch
__device__ float g_ssq[BB * NH];         // sum of p^2 per (b,h)
__device__ float g_is [BB * NH];         // 1/sqrt(var+eps) per (b,h)
__device__ float g_wqt[DD * DD];         // transposed weights [N,K]
__device__ float g_wkt[DD * DD];
__device__ float g_wvt[DD * DD];
__device__ float g_wot[DD * DD];

__device__ __forceinline__ uint32_t f2tf32(float f) {
    uint32_t r;
    asm("cvt.rna.tf32.f32 %0, %1;" : "=r"(r) : "f"(f));
    return r;
}

__device__ __forceinline__ void mma_16n8k8(
    float* d, const uint32_t* a, const uint32_t* b)
{
    asm volatile(
        "mma.sync.aligned.m16n8k8.row.col.f32.tf32.tf32.f32 "
        "{%0,%1,%2,%3}, {%4,%5,%6,%7}, {%8,%9}, {%0,%1,%2,%3};"
        : "+f"(d[0]), "+f"(d[1]), "+f"(d[2]), "+f"(d[3])
        : "r"(a[0]), "r"(a[1]), "r"(a[2]), "r"(a[3]),
          "r"(b[0]), "r"(b[1]));
}

// ---------------------------------------------------------------------------
// Warp-MMA tf32 GEMM: C = A(MxK) @ Bt^T + bias,  Bt is [N,K] row-major.
// CTA 128x128, BK=32, 8 warps (2x4), warp tile 64x32 (4x4 m16n8k8 frags).
// ---------------------------------------------------------------------------
#define GM_PAD 36

__global__ __launch_bounds__(256, 2) void gemm_mma(
    const float* __restrict__ A, const float* __restrict__ Bt,
    const float* __restrict__ bias, float* __restrict__ C,
    int M, int N, int K)
{
    __shared__ uint32_t As[128 * GM_PAD];
    __shared__ uint32_t Bs[128 * GM_PAD];

    const int tid  = threadIdx.x;
    const int wid  = tid >> 5, lane = tid & 31;
    const int gid  = lane >> 2, tig = lane & 3;
    const int m_w  = (wid & 1) * 64;
    const int n_w  = (wid >> 1) * 32;
    const int m0   = blockIdx.y * 128;
    const int n0   = blockIdx.x * 128;

    const int lr = tid >> 1;            // 0..127
    const int lc = (tid & 1) * 16;      // 0 or 16

    float acc[4][4][4];
#pragma unroll
    for (int mi = 0; mi < 4; mi++)
#pragma unroll
        for (int ni = 0; ni < 4; ni++)
#pragma unroll
            for (int r = 0; r < 4; r++) acc[mi][ni][r] = 0.f;

    for (int k0 = 0; k0 < K; k0 += 32) {
        float4 av[4], bv[4];
#pragma unroll
        for (int j = 0; j < 4; j++) {
            av[j] = *(const float4*)&A [(size_t)(m0 + lr) * K + k0 + lc + j * 4];
            bv[j] = *(const float4*)&Bt[(size_t)(n0 + lr) * K + k0 + lc + j * 4];
        }
        __syncthreads();
#pragma unroll
        for (int j = 0; j < 4; j++) {
            uint32_t* ap = &As[lr * GM_PAD + lc + j * 4];
            ap[0] = f2tf32(av[j].x); ap[1] = f2tf32(av[j].y);
            ap[2] = f2tf32(av[j].z); ap[3] = f2tf32(av[j].w);
            uint32_t* bp = &Bs[lr * GM_PAD + lc + j * 4];
            bp[0] = f2tf32(bv[j].x); bp[1] = f2tf32(bv[j].y);
            bp[2] = f2tf32(bv[j].z); bp[3] = f2tf32(bv[j].w);
        }
        __syncthreads();

#pragma unroll
        for (int ks = 0; ks < 4; ks++) {
            const int kk = ks * 8;
            uint32_t af[4][4], bf[4][2];
#pragma unroll
            for (int mi = 0; mi < 4; mi++) {
                int r = m_w + mi * 16 + gid;
                af[mi][0] = As[r * GM_PAD + kk + tig];
                af[mi][1] = As[(r + 8) * GM_PAD + kk + tig];
                af[mi][2] = As[r * GM_PAD + kk + tig + 4];
                af[mi][3] = As[(r + 8) * GM_PAD + kk + tig + 4];
            }
#pragma unroll
            for (int ni = 0; ni < 4; ni++) {
                int r = n_w + ni * 8 + gid;
                bf[ni][0] = Bs[r * GM_PAD + kk + tig];
                bf[ni][1] = Bs[r * GM_PAD + kk + tig + 4];
            }
#pragma unroll
            for (int mi = 0; mi < 4; mi++)
#pragma unroll
                for (int ni = 0; ni < 4; ni++)
                    mma_16n8k8(acc[mi][ni], af[mi], bf[ni]);
        }
    }

    // epilogue + bias
#pragma unroll
    for (int mi = 0; mi < 4; mi++) {
        const int r0 = m0 + m_w + mi * 16 + gid;
        const int r1 = r0 + 8;
#pragma unroll
        for (int ni = 0; ni < 4; ni++) {
            const int col = n0 + n_w + ni * 8 + tig * 2;
            float2 bz = *(const float2*)&bias[col];
            float2 o0 = make_float2(acc[mi][ni][0] + bz.x, acc[mi][ni][1] + bz.y);
            float2 o1 = make_float2(acc[mi][ni][2] + bz.x, acc[mi][ni][3] + bz.y);
            *(float2*)&C[(size_t)r0 * N + col] = o0;
            *(float2*)&C[(size_t)r1 * N + col] = o1;
        }
    }
}

// ---------------------------------------------------------------------------
// 512x512 transpose: Wt[n,k] = W[k,n]
// ---------------------------------------------------------------------------
__global__ void transpose512(const float* __restrict__ W, float* __restrict__ Wt)
{
    __shared__ float t[32][33];
    const int bx = blockIdx.x * 32, by = blockIdx.y * 32;
    const int tx = threadIdx.x, ty = threadIdx.y;   // 32 x 8
#pragma unroll
    for (int i = 0; i < 32; i += 8)
        t[ty + i][tx] = W[(size_t)(by + ty + i) * DD + bx + tx];
    __syncthreads();
#pragma unroll
    for (int i = 0; i < 32; i += 8)
        Wt[(size_t)(bx + ty + i) * DD + by + tx] = t[tx][ty + i];
}

// ---------------------------------------------------------------------------
// Depthwise 4x4 stride-3 conv (pad 1) + LayerNorm over channels.
// ---------------------------------------------------------------------------
__global__ __launch_bounds__(256) void convln_kernel(
    const float* __restrict__ q, const float* __restrict__ srw,
    const float* __restrict__ srb, const float* __restrict__ lng,
    const float* __restrict__ lnb)
{
    const int b  = blockIdx.y;
    const int op = blockIdx.x;
    const int oh = op >> 4, ow = op & 15;
    const int tid = threadIdx.x;
    const int c0 = tid, c1 = tid + 256;

    float a0 = srb[c0], a1 = srb[c1];
#pragma unroll
    for (int kh = 0; kh < 4; kh++) {
        int ih = oh * 3 - 1 + kh;
        if (ih < 0 || ih >= HHH) continue;
#pragma unroll
        for (int kw = 0; kw < 4; kw++) {
            int iw = ow * 3 - 1 + kw;
            if (iw < 0 || iw >= HHH) continue;
            const float* qr = q + ((size_t)b * NQ + ih * HHH + iw) * DD;
            a0 += srw[c0 * 16 + kh * 4 + kw] * qr[c0];
            a1 += srw[c1 * 16 + kh * 4 + kw] * qr[c1];
        }
    }

    float s  = a0 + a1;
    float s2 = a0 * a0 + a1 * a1;
#pragma unroll
    for (int off = 16; off; off >>= 1) {
        s  += __shfl_xor_sync(0xFFFFFFFFu, s,  off);
        s2 += __shfl_xor_sync(0xFFFFFFFFu, s2, off);
    }
    __shared__ float rs[8], rs2[8];
    if ((tid & 31) == 0) { rs[tid >> 5] = s; rs2[tid >> 5] = s2; }
    __syncthreads();
    if (tid == 0) {
        float ts = 0.f, ts2 = 0.f;
#pragma unroll
        for (int i = 0; i < 8; i++) { ts += rs[i]; ts2 += rs2[i]; }
        rs[0] = ts; rs2[0] = ts2;
    }
    __syncthreads();
    const float mu   = rs[0] * (1.f / 512.f);
    const float var  = rs2[0] * (1.f / 512.f) - mu * mu;
    const float rstd = rsqrtf(var + 1e-5f);

    float* xo = g_x + ((size_t)b * NKK + op) * DD;
    xo[c0] = (a0 - mu) * rstd * lng[c0] + lnb[c0];
    xo[c1] = (a1 - mu) * rstd * lng[c1] + lnb[c1];
}

__global__ void vcolsum_kernel()
{
    const int b = blockIdx.x;
    const int c = threadIdx.x;
    float s = 0.f;
    for (int k = 0; k < NKK; k++)
        s += g_vp[((size_t)b * NKK + k) * DD + c];
    g_vs[b * DD + c] = s;
}

__global__ void zero_ssq_kernel()
{
    if (threadIdx.x < BB * NH) g_ssq[threadIdx.x] = 0.f;
}

__global__ void stats_kernel()
{
    const int i = threadIdx.x;
    if (i < BB * NH) {
        const float m = 1.f / 256.f;
        float va = g_ssq[i] / (2304.f * 256.f) - m * m;
        g_is[i] = rsqrtf(va + 1e-5f);
    }
}

__global__ void norm_kernel()
{
    const float m = 1.f / 256.f;
    int idx = blockIdx.x * 256 + threadIdx.x;
    const int total = BB * NQ * DD;
    if (idx < total) {
        int c = idx & 511;
        int b = idx / (NQ * DD);
        int h = c >> 6;
        g_ou[idx] = (g_ou[idx] - m * g_vs[b * DD + c]) * g_is[b * NH + h];
    }
}

// ---------------------------------------------------------------------------
// Fused attention (unchanged from passing round)
// ---------------------------------------------------------------------------
#define SC_STRIDE 257
#define RW 513
#define ATT_SMEM_FLOATS (16 * 8 * SC_STRIDE + 2 * 16 * RW + 64 + 8 + 8)

__global__ __launch_bounds__(256, 1) void attn_kernel(
    const float* __restrict__ tw, const float* __restrict__ tb)
{
    extern __shared__ float sm[];
    float* sc  = sm;
    float* qs  = sc  + 16 * 8 * SC_STRIDE;
    float* ks  = qs  + 16 * RW;
    float* tws = ks  + 16 * RW;
    float* tbs = tws + 64;
    float* ssq = tbs + 8;

    const int tid = threadIdx.x;
    const int b   = blockIdx.y;
    const int q0  = blockIdx.x * 16;

    if (tid < 64) tws[tid] = tw[tid];
    if (tid < 8) { tbs[tid] = tb[tid]; ssq[tid] = 0.f; }

    {
        const float* qp = g_qp + ((size_t)b * NQ + q0) * DD;
        for (int idx = tid; idx < 2048; idx += 256) {
            int r  = idx >> 7;
            int c4 = (idx & 127) << 2;
            float4 v = *(const float4*)&qp[r * DD + c4];
            float* d = &qs[r * RW + c4];
            d[0] = v.x; d[1] = v.y; d[2] = v.z; d[3] = v.w;
        }
    }

    const int qq = tid >> 4;
    const int kl = tid & 15;
    for (int kc = 0; kc < 16; kc++) {
        __syncthreads();
        const float* kp = g_kp + ((size_t)b * NKK + kc * 16) * DD;
        for (int idx = tid; idx < 2048; idx += 256) {
            int r  = idx >> 7;
            int c4 = (idx & 127) << 2;
            float4 v = *(const float4*)&kp[r * DD + c4];
            float* d = &ks[r * RW + c4];
            d[0] = v.x; d[1] = v.y; d[2] = v.z; d[3] = v.w;
        }
        __syncthreads();
        const float* qrow = qs + qq * RW;
        const float* krow = ks + kl * RW;
        float acc[8];
#pragma unroll
        for (int h = 0; h < 8; h++) {
            float a = 0.f;
#pragma unroll
            for (int cc = 0; cc < 64; cc++)
                a += qrow[h * 64 + cc] * krow[h * 64 + cc];
            acc[h] = a;
        }
        const int k = kc * 16 + kl;
#pragma unroll
        for (int h = 0; h < 8; h++)
            sc[(qq * 8 + h) * SC_STRIDE + k] = acc[h] * 0.125f;
    }
    __syncthreads();

    {
        const int k = tid;
        for (int q = 0; q < 16; q++) {
            float r[8];
#pragma unroll
            for (int i = 0; i < 8; i++) r[i] = sc[(q * 8 + i) * SC_STRIDE + k];
            float o_[8];
#pragma unroll
            for (int o = 0; o < 8; o++) {
                float s = tbs[o];
#pragma unroll
                for (int i = 0; i < 8; i++) s += tws[o * 8 + i] * r[i];
                o_[o] = s;
            }
#pragma unroll
            for (int o = 0; o < 8; o++) sc[(q * 8 + o) * SC_STRIDE + k] = o_[o];
        }
    }
    __syncthreads();

    if (tid < 128) {
        float* row = sc + tid * SC_STRIDE;
        float mx = -1e30f;
        for (int k = 0; k < 256; k++) mx = fmaxf(mx, row[k]);
        float s = 0.f;
        for (int k = 0; k < 256; k++) { float e = expf(row[k] - mx); row[k] = e; s += e; }
        float inv = 1.f / s;
        float lss = 0.f;
        for (int k = 0; k < 256; k++) { float p = row[k] * inv; row[k] = p; lss += p * p; }
        atomicAdd(&ssq[tid & 7], lss);
    }
    __syncthreads();
    if (tid < 8) atomicAdd(&g_ssq[b * NH + tid], ssq[tid]);

    const int qg = tid >> 6;
    const int cg = tid & 63;
    const int o  = cg >> 3;
    float acc2[4][8];
#pragma unroll
    for (int i = 0; i < 4; i++)
#pragma unroll
        for (int j = 0; j < 8; j++) acc2[i][j] = 0.f;

    for (int vc = 0; vc < 16; vc++) {
        __syncthreads();
        const float* vp = g_vp + ((size_t)b * NKK + vc * 16) * DD;
        for (int idx = tid; idx < 2048; idx += 256) {
            int r  = idx >> 7;
            int c4 = (idx & 127) << 2;
            float4 v = *(const float4*)&vp[r * DD + c4];
            float* d = &ks[r * RW + c4];
            d[0] = v.x; d[1] = v.y; d[2] = v.z; d[3] = v.w;
        }
        __syncthreads();
#pragma unroll
        for (int kl2 = 0; kl2 < 16; kl2++) {
            const int k = vc * 16 + kl2;
            float pv[8];
#pragma unroll
            for (int j = 0; j < 8; j++) pv[j] = ks[kl2 * RW + cg * 8 + j];
#pragma unroll
            for (int q4 = 0; q4 < 4; q4++) {
                float p = sc[((qg * 4 + q4) * 8 + o) * SC_STRIDE + k];
#pragma unroll
                for (int j = 0; j < 8; j++) acc2[q4][j] += p * pv[j];
            }
        }
    }

#pragma unroll
    for (int q4 = 0; q4 < 4; q4++) {
        float* outp = g_ou + ((size_t)b * NQ + q0 + qg * 4 + q4) * DD + cg * 8;
        float4 c0 = make_float4(acc2[q4][0], acc2[q4][1], acc2[q4][2], acc2[q4][3]);
        float4 c1 = make_float4(acc2[q4][4], acc2[q4][5], acc2[q4][6], acc2[q4][7]);
        *(float4*)&outp[0] = c0;
        *(float4*)&outp[4] = c1;
    }
}

// ---------------------------------------------------------------------------
extern "C" void kernel_launch(void* const* d_in, const int* in_sizes, int n_in,
                              void* d_out, int out_size)
{
    (void)in_sizes; (void)n_in; (void)out_size;
    const float* queries = (const float*)d_in[0];
    const float* Wq = (const float*)d_in[1];
    const float* bq = (const float*)d_in[2];
    const float* Wk = (const float*)d_in[3];
    const float* bk = (const float*)d_in[4];
    const float* Wv = (const float*)d_in[5];
    const float* bv = (const float*)d_in[6];
    const float* Wo = (const float*)d_in[7];
    const float* bo = (const float*)d_in[8];
    const float* srw = (const float*)d_in[9];
    const float* srb = (const float*)d_in[10];
    const float* lng = (const float*)d_in[11];
    const float* lnb = (const float*)d_in[12];
    const float* tw  = (const float*)d_in[13];
    const float* tb  = (const float*)d_in[14];
    float* out = (float*)d_out;

    float *qp, *x, *kp, *vp, *ou, *wqt, *wkt, *wvt, *wot;
    cudaGetSymbolAddress((void**)&qp,  g_qp);
    cudaGetSymbolAddress((void**)&x,   g_x);
    cudaGetSymbolAddress((void**)&kp,  g_kp);
    cudaGetSymbolAddress((void**)&vp,  g_vp);
    cudaGetSymbolAddress((void**)&ou,  g_ou);
    cudaGetSymbolAddress((void**)&wqt, g_wqt);
    cudaGetSymbolAddress((void**)&wkt, g_wkt);
    cudaGetSymbolAddress((void**)&wvt, g_wvt);
    cudaGetSymbolAddress((void**)&wot, g_wot);

    const size_t attn_smem = ATT_SMEM_FLOATS * sizeof(float);
    cudaFuncSetAttribute(attn_kernel,
                         cudaFuncAttributeMaxDynamicSharedMemorySize,
                         (int)attn_smem);

    zero_ssq_kernel<<<1, 128>>>();

    // transpose weights: Wt[n,k] = W[k,n]
    dim3 tg(16, 16), tb2(32, 8);
    transpose512<<<tg, tb2>>>(Wq, wqt);
    transpose512<<<tg, tb2>>>(Wk, wkt);
    transpose512<<<tg, tb2>>>(Wv, wvt);
    transpose512<<<tg, tb2>>>(Wo, wot);

    // Q projection: (36864, 512) @ (512, 512)
    gemm_mma<<<dim3(4, 288), 256>>>(queries, wqt, bq, qp, BB * NQ, DD, DD);

    // spatial reduction conv + LN
    convln_kernel<<<dim3(256, 16), 256>>>(queries, srw, srb, lng, lnb);

    // K, V projections: (4096, 512) @ (512, 512)
    gemm_mma<<<dim3(4, 32), 256>>>(x, wkt, bk, kp, BB * NKK, DD, DD);
    gemm_mma<<<dim3(4, 32), 256>>>(x, wvt, bv, vp, BB * NKK, DD, DD);

    vcolsum_kernel<<<BB, 512>>>();

    // fused attention
    attn_kernel<<<dim3(NQ / 16, BB), 256, attn_smem>>>(tw, tb);

    stats_kernel<<<1, 128>>>();

    // normalize (InstanceNorm folded into output)
    norm_kernel<<<(BB * NQ * DD + 255) / 256, 256>>>();

    // output projection -> d_out
    gemm_mma<<<dim3(4, 288), 256>>>(ou, wot, bo, out, BB * NQ, DD, DD);
}

// round 5
// speedup vs baseline: 1.4337x; 1.1855x over previous
#include <cuda_runtime.h>
#include <math.h>
#include <cstdint>

// Problem constants
#define BB   16
#define NQ   2304
#define DD   512
#define NH   8
#define DK   64
#define NKK  256
#define HHH  48

// Scratch (device globals; allocation-free per harness rules)
__device__ float g_qp[BB * NQ * DD];     // Q projection
__device__ float g_x [BB * NKK * DD];    // conv+LN output
__device__ float g_kp[BB * NKK * DD];    // K projection
__device__ float g_vp[BB * NKK * DD];    // V projection
__device__ float g_ou[BB * NQ * DD];     // unnormalized attention output
__device__ float g_vs[BB * DD];          // column sums of V per batch
__device__ float g_ssq[BB * NH];         // sum of p^2 per (b,h)
__device__ float g_is [BB * NH];         // 1/sqrt(var+eps) per (b,h)
__device__ float g_wqt[DD * DD];         // transposed weights [N,K]
__device__ float g_wkt[DD * DD];
__device__ float g_wvt[DD * DD];
__device__ float g_wot[DD * DD];

__device__ __forceinline__ uint32_t f2tf32(float f) {
    uint32_t r;
    asm("cvt.rna.tf32.f32 %0, %1;" : "=r"(r) : "f"(f));
    return r;
}
__device__ __forceinline__ void split_tf32(float x, uint32_t& hi, uint32_t& lo) {
    hi = __float_as_uint(x) & 0xffffe000u;
    lo = f2tf32(x - __uint_as_float(hi));
}

__device__ __forceinline__ void mma_16n8k8(
    float* d, const uint32_t* a, const uint32_t* b)
{
    asm volatile(
        "mma.sync.aligned.m16n8k8.row.col.f32.tf32.tf32.f32 "
        "{%0,%1,%2,%3}, {%4,%5,%6,%7}, {%8,%9}, {%0,%1,%2,%3};"
        : "+f"(d[0]), "+f"(d[1]), "+f"(d[2]), "+f"(d[3])
        : "r"(a[0]), "r"(a[1]), "r"(a[2]), "r"(a[3]),
          "r"(b[0]), "r"(b[1]));
}

#define CP_A16(dst, src) \
    asm volatile("cp.async.cg.shared.global [%0], [%1], 16;" \
                 :: "r"(dst), "l"(src))
#define CP_COMMIT() asm volatile("cp.async.commit_group;" ::: "memory")
#define CP_WAIT1()  asm volatile("cp.async.wait_group 1;" ::: "memory")
#define CP_WAIT0()  asm volatile("cp.async.wait_group 0;" ::: "memory")

__device__ __forceinline__ uint32_t smem_u32(const void* p) {
    uint32_t a;
    asm("{ .reg .u64 t; cvta.to.shared.u64 t, %1; cvt.u32.u64 %0, t; }"
        : "=r"(a) : "l"(p));
    return a;
}

// ---------------------------------------------------------------------------
// Warp-MMA 3xTF32 GEMM (fp32 accuracy): C = A(MxK) @ Bt^T + bias.
// Bt is [N,K] row-major. CTA 128x128, BK=32, 8 warps, warp tile 64x32.
// Double-buffered via cp.async. Dynamic smem: 2 bufs x (A+B) x 128x36 floats.
// ---------------------------------------------------------------------------
#define GM_PAD 36
#define GM_BUF (128 * GM_PAD)            // floats per matrix per buffer
#define GM_SMEM (4 * GM_BUF * 4)         // bytes: 2 bufs x (A,B)

__global__ __launch_bounds__(256, 2) void gemm_mma(
    const float* __restrict__ A, const float* __restrict__ Bt,
    const float* __restrict__ bias, float* __restrict__ C,
    int M, int N, int K)
{
    extern __shared__ float gsm[];
    // layout: [buf0 A][buf0 B][buf1 A][buf1 B]
    const int tid  = threadIdx.x;
    const int wid  = tid >> 5, lane = tid & 31;
    const int gid  = lane >> 2, tig = lane & 3;
    const int m_w  = (wid & 1) * 64;
    const int n_w  = (wid >> 1) * 32;
    const int m0   = blockIdx.y * 128;
    const int n0   = blockIdx.x * 128;

    const int lr = tid >> 1;            // 0..127
    const int lc = (tid & 1) * 16;      // 0 or 16
    const uint32_t sbase = smem_u32(gsm);

    float acc[4][4][4];
#pragma unroll
    for (int mi = 0; mi < 4; mi++)
#pragma unroll
        for (int ni = 0; ni < 4; ni++)
#pragma unroll
            for (int r = 0; r < 4; r++) acc[mi][ni][r] = 0.f;

    const int nch = K >> 5;

    // async-copy one 32-K chunk into buffer `buf`
    auto issue = [&](int c, int buf) {
        const float* Ac = A  + (size_t)(m0 + lr) * K + c * 32 + lc;
        const float* Bc = Bt + (size_t)(n0 + lr) * K + c * 32 + lc;
        uint32_t da = sbase + (uint32_t)(buf * 2 * GM_BUF + lr * GM_PAD + lc) * 4;
        uint32_t db = da + GM_BUF * 4;
#pragma unroll
        for (int j = 0; j < 4; j++) {
            CP_A16(da + j * 16, Ac + j * 4);
            CP_A16(db + j * 16, Bc + j * 4);
        }
    };

    issue(0, 0);
    CP_COMMIT();

    for (int c = 0; c < nch; c++) {
        if (c + 1 < nch) {
            issue(c + 1, (c + 1) & 1);
            CP_COMMIT();
            CP_WAIT1();
        } else {
            CP_WAIT0();
        }
        __syncthreads();

        const float* As = gsm + (c & 1) * 2 * GM_BUF;
        const float* Bs = As + GM_BUF;

#pragma unroll
        for (int ks = 0; ks < 4; ks++) {
            const int kk = ks * 8;
            uint32_t bh[4][2], bl[4][2];
#pragma unroll
            for (int ni = 0; ni < 4; ni++) {
                int r = n_w + ni * 8 + gid;
                split_tf32(Bs[r * GM_PAD + kk + tig],     bh[ni][0], bl[ni][0]);
                split_tf32(Bs[r * GM_PAD + kk + tig + 4], bh[ni][1], bl[ni][1]);
            }
#pragma unroll
            for (int mi = 0; mi < 4; mi++) {
                uint32_t ah[4], al[4];
                int r0 = m_w + mi * 16 + gid;
                split_tf32(As[r0 * GM_PAD + kk + tig],           ah[0], al[0]);
                split_tf32(As[(r0 + 8) * GM_PAD + kk + tig],     ah[1], al[1]);
                split_tf32(As[r0 * GM_PAD + kk + tig + 4],       ah[2], al[2]);
                split_tf32(As[(r0 + 8) * GM_PAD + kk + tig + 4], ah[3], al[3]);
#pragma unroll
                for (int ni = 0; ni < 4; ni++) {
                    mma_16n8k8(acc[mi][ni], al, bh[ni]);
                    mma_16n8k8(acc[mi][ni], ah, bl[ni]);
                    mma_16n8k8(acc[mi][ni], ah, bh[ni]);
                }
            }
        }
        __syncthreads();
    }

    // epilogue + bias
#pragma unroll
    for (int mi = 0; mi < 4; mi++) {
        const int r0 = m0 + m_w + mi * 16 + gid;
        const int r1 = r0 + 8;
#pragma unroll
        for (int ni = 0; ni < 4; ni++) {
            const int col = n0 + n_w + ni * 8 + tig * 2;
            float2 bz = *(const float2*)&bias[col];
            float2 o0 = make_float2(acc[mi][ni][0] + bz.x, acc[mi][ni][1] + bz.y);
            float2 o1 = make_float2(acc[mi][ni][2] + bz.x, acc[mi][ni][3] + bz.y);
            *(float2*)&C[(size_t)r0 * N + col] = o0;
            *(float2*)&C[(size_t)r1 * N + col] = o1;
        }
    }
}

// ---------------------------------------------------------------------------
// 512x512 transpose: Wt[n,k] = W[k,n]
// ---------------------------------------------------------------------------
__global__ void transpose512(const float* __restrict__ W, float* __restrict__ Wt)
{
    __shared__ float t[32][33];
    const int bx = blockIdx.x * 32, by = blockIdx.y * 32;
    const int tx = threadIdx.x, ty = threadIdx.y;   // 32 x 8
#pragma unroll
    for (int i = 0; i < 32; i += 8)
        t[ty + i][tx] = W[(size_t)(by + ty + i) * DD + bx + tx];
    __syncthreads();
#pragma unroll
    for (int i = 0; i < 32; i += 8)
        Wt[(size_t)(bx + ty + i) * DD + by + tx] = t[tx][ty + i];
}

// ---------------------------------------------------------------------------
// Depthwise 4x4 stride-3 conv (pad 1) + LayerNorm over channels.
// ---------------------------------------------------------------------------
__global__ __launch_bounds__(256) void convln_kernel(
    const float* __restrict__ q, const float* __restrict__ srw,
    const float* __restrict__ srb, const float* __restrict__ lng,
    const float* __restrict__ lnb)
{
    const int b  = blockIdx.y;
    const int op = blockIdx.x;
    const int oh = op >> 4, ow = op & 15;
    const int tid = threadIdx.x;
    const int c0 = tid, c1 = tid + 256;

    float a0 = srb[c0], a1 = srb[c1];
#pragma unroll
    for (int kh = 0; kh < 4; kh++) {
        int ih = oh * 3 - 1 + kh;
        if (ih < 0 || ih >= HHH) continue;
#pragma unroll
        for (int kw = 0; kw < 4; kw++) {
            int iw = ow * 3 - 1 + kw;
            if (iw < 0 || iw >= HHH) continue;
            const float* qr = q + ((size_t)b * NQ + ih * HHH + iw) * DD;
            a0 += srw[c0 * 16 + kh * 4 + kw] * qr[c0];
            a1 += srw[c1 * 16 + kh * 4 + kw] * qr[c1];
        }
    }

    float s  = a0 + a1;
    float s2 = a0 * a0 + a1 * a1;
#pragma unroll
    for (int off = 16; off; off >>= 1) {
        s  += __shfl_xor_sync(0xFFFFFFFFu, s,  off);
        s2 += __shfl_xor_sync(0xFFFFFFFFu, s2, off);
    }
    __shared__ float rs[8], rs2[8];
    if ((tid & 31) == 0) { rs[tid >> 5] = s; rs2[tid >> 5] = s2; }
    __syncthreads();
    if (tid == 0) {
        float ts = 0.f, ts2 = 0.f;
#pragma unroll
        for (int i = 0; i < 8; i++) { ts += rs[i]; ts2 += rs2[i]; }
        rs[0] = ts; rs2[0] = ts2;
    }
    __syncthreads();
    const float mu   = rs[0] * (1.f / 512.f);
    const float var  = rs2[0] * (1.f / 512.f) - mu * mu;
    const float rstd = rsqrtf(var + 1e-5f);

    float* xo = g_x + ((size_t)b * NKK + op) * DD;
    xo[c0] = (a0 - mu) * rstd * lng[c0] + lnb[c0];
    xo[c1] = (a1 - mu) * rstd * lng[c1] + lnb[c1];
}

__global__ void vcolsum_kernel()
{
    const int b = blockIdx.x;
    const int c = threadIdx.x;
    float s = 0.f;
    for (int k = 0; k < NKK; k++)
        s += g_vp[((size_t)b * NKK + k) * DD + c];
    g_vs[b * DD + c] = s;
}

__global__ void zero_ssq_kernel()
{
    if (threadIdx.x < BB * NH) g_ssq[threadIdx.x] = 0.f;
}

__global__ void stats_kernel()
{
    const int i = threadIdx.x;
    if (i < BB * NH) {
        const float m = 1.f / 256.f;
        float va = g_ssq[i] / (2304.f * 256.f) - m * m;
        g_is[i] = rsqrtf(va + 1e-5f);
    }
}

__global__ void norm_kernel()
{
    const float m = 1.f / 256.f;
    int idx = blockIdx.x * 256 + threadIdx.x;
    const int total = BB * NQ * DD;
    if (idx < total) {
        int c = idx & 511;
        int b = idx / (NQ * DD);
        int h = c >> 6;
        g_ou[idx] = (g_ou[idx] - m * g_vs[b * DD + c]) * g_is[b * NH + h];
    }
}

// ---------------------------------------------------------------------------
// Fused attention v2: register-tiled fp32.
// Block = (b, 16-query tile), 256 threads, warp = head.
// smem: sc[128][257], qs[16][516], ks[16][516] (K then V), tw/tb/ssq.
// ---------------------------------------------------------------------------
#define SC_STRIDE 257
#define RW 516
#define ATT_SMEM_FLOATS (128 * SC_STRIDE + 2 * 16 * RW + 64 + 8 + 8)

__global__ __launch_bounds__(256, 1) void attn_kernel(
    const float* __restrict__ tw, const float* __restrict__ tb)
{
    extern __shared__ float sm[];
    float* sc  = sm;                         // 128 * 257
    float* qs  = sc  + 128 * SC_STRIDE;      // 16 * 516
    float* ks  = qs  + 16 * RW;              // 16 * 516 (K chunk, reused for V)
    float* tws = ks  + 16 * RW;              // 64
    float* tbs = tws + 64;                   // 8
    float* ssq = tbs + 8;                    // 8

    const int tid  = threadIdx.x;
    const int wid  = tid >> 5;               // warp = head
    const int lane = tid & 31;
    const int b    = blockIdx.y;
    const int q0   = blockIdx.x * 16;

    if (tid < 64) tws[tid] = tw[tid];
    if (tid < 8) { tbs[tid] = tb[tid]; ssq[tid] = 0.f; }

    // load Q tile (16 x 512)
    {
        const float* qp = g_qp + ((size_t)b * NQ + q0) * DD;
        for (int idx = tid; idx < 2048; idx += 256) {
            int r  = idx >> 7;
            int c4 = (idx & 127) << 2;
            *(float4*)&qs[r * RW + c4] = *(const float4*)&qp[r * DD + c4];
        }
    }

    // ---- QK: warp h computes S_h[16][256]; thread tile 4q x 2k ----
    {
        const int h  = wid;
        const int qg = lane >> 3;    // 0..3 -> q rows qg*4..+4
        const int kg = lane & 7;     // 0..7 -> k pair kg*2, kg*2+1
        for (int kc = 0; kc < 16; kc++) {
            __syncthreads();
            const float* kp = g_kp + ((size_t)b * NKK + kc * 16) * DD;
            for (int idx = tid; idx < 2048; idx += 256) {
                int r  = idx >> 7;
                int c4 = (idx & 127) << 2;
                *(float4*)&ks[r * RW + c4] = *(const float4*)&kp[r * DD + c4];
            }
            __syncthreads();

            float acc[4][2];
#pragma unroll
            for (int i = 0; i < 4; i++) { acc[i][0] = 0.f; acc[i][1] = 0.f; }

            const float* qbase = qs + (qg * 4) * RW + h * 64;
            const float* kbase = ks + (kg * 2) * RW + h * 64;
#pragma unroll
            for (int d4 = 0; d4 < 16; d4++) {
                float4 kv0 = *(const float4*)&kbase[d4 * 4];
                float4 kv1 = *(const float4*)&kbase[RW + d4 * 4];
#pragma unroll
                for (int i = 0; i < 4; i++) {
                    float4 qv = *(const float4*)&qbase[i * RW + d4 * 4];
                    acc[i][0] += qv.x * kv0.x + qv.y * kv0.y
                               + qv.z * kv0.z + qv.w * kv0.w;
                    acc[i][1] += qv.x * kv1.x + qv.y * kv1.y
                               + qv.z * kv1.z + qv.w * kv1.w;
                }
            }
            const int kb = kc * 16 + kg * 2;
#pragma unroll
            for (int i = 0; i < 4; i++) {
                float* row = sc + ((qg * 4 + i) * 8 + h) * SC_STRIDE;
                row[kb]     = acc[i][0] * 0.125f;
                row[kb + 1] = acc[i][1] * 0.125f;
            }
        }
    }
    __syncthreads();

    // ---- head mixing: s2[o][k] = tb[o] + sum_i tw[o][i]*s[i][k] ----
    {
        const int k = tid;  // 0..255
        for (int q = 0; q < 16; q++) {
            float r[8];
#pragma unroll
            for (int i = 0; i < 8; i++) r[i] = sc[(q * 8 + i) * SC_STRIDE + k];
            float o_[8];
#pragma unroll
            for (int o = 0; o < 8; o++) {
                float s = tbs[o];
#pragma unroll
                for (int i = 0; i < 8; i++) s += tws[o * 8 + i] * r[i];
                o_[o] = s;
            }
#pragma unroll
            for (int o = 0; o < 8; o++) sc[(q * 8 + o) * SC_STRIDE + k] = o_[o];
        }
    }
    __syncthreads();

    // ---- softmax per (q,o) row + sum of squares ----
    if (tid < 128) {
        float* row = sc + tid * SC_STRIDE;
        float mx = -1e30f;
#pragma unroll 4
        for (int k = 0; k < 256; k++) mx = fmaxf(mx, row[k]);
        float s = 0.f;
#pragma unroll 4
        for (int k = 0; k < 256; k++) { float e = expf(row[k] - mx); row[k] = e; s += e; }
        float inv = 1.f / s;
        float lss = 0.f;
#pragma unroll 4
        for (int k = 0; k < 256; k++) { float p = row[k] * inv; row[k] = p; lss += p * p; }
        atomicAdd(&ssq[tid & 7], lss);
    }
    __syncthreads();
    if (tid < 8) atomicAdd(&g_ssq[b * NH + tid], ssq[tid]);

    // ---- P @ V: warp h, thread tile 4q x (4+4)j ----
    {
        const int h  = wid;
        const int qg = lane >> 3;    // 0..3
        const int jg = lane & 7;     // 0..7 -> cols jg*4..+4 and +32
        float4 a0[4], a1[4];
#pragma unroll
        for (int i = 0; i < 4; i++) {
            a0[i] = make_float4(0.f, 0.f, 0.f, 0.f);
            a1[i] = make_float4(0.f, 0.f, 0.f, 0.f);
        }

        for (int vc = 0; vc < 16; vc++) {
            __syncthreads();
            const float* vp = g_vp + ((size_t)b * NKK + vc * 16) * DD;
            for (int idx = tid; idx < 2048; idx += 256) {
                int r  = idx >> 7;
                int c4 = (idx & 127) << 2;
                *(float4*)&ks[r * RW + c4] = *(const float4*)&vp[r * DD + c4];
            }
            __syncthreads();

            const float* vbase = ks + h * 64 + jg * 4;
#pragma unroll
            for (int kl = 0; kl < 16; kl++) {
                float4 v0 = *(const float4*)&vbase[kl * RW];
                float4 v1 = *(const float4*)&vbase[kl * RW + 32];
                const int k = vc * 16 + kl;
#pragma unroll
                for (int i = 0; i < 4; i++) {
                    float p = sc[((qg * 4 + i) * 8 + h) * SC_STRIDE + k];
                    a0[i].x += p * v0.x; a0[i].y += p * v0.y;
                    a0[i].z += p * v0.z; a0[i].w += p * v0.w;
                    a1[i].x += p * v1.x; a1[i].y += p * v1.y;
                    a1[i].z += p * v1.z; a1[i].w += p * v1.w;
                }
            }
        }

#pragma unroll
        for (int i = 0; i < 4; i++) {
            float* outp = g_ou + ((size_t)b * NQ + q0 + qg * 4 + i) * DD
                        + h * 64 + jg * 4;
            *(float4*)outp        = a0[i];
            *(float4*)(outp + 32) = a1[i];
        }
    }
}

// ---------------------------------------------------------------------------
extern "C" void kernel_launch(void* const* d_in, const int* in_sizes, int n_in,
                              void* d_out, int out_size)
{
    (void)in_sizes; (void)n_in; (void)out_size;
    const float* queries = (const float*)d_in[0];
    const float* Wq = (const float*)d_in[1];
    const float* bq = (const float*)d_in[2];
    const float* Wk = (const float*)d_in[3];
    const float* bk = (const float*)d_in[4];
    const float* Wv = (const float*)d_in[5];
    const float* bv = (const float*)d_in[6];
    const float* Wo = (const float*)d_in[7];
    const float* bo = (const float*)d_in[8];
    const float* srw = (const float*)d_in[9];
    const float* srb = (const float*)d_in[10];
    const float* lng = (const float*)d_in[11];
    const float* lnb = (const float*)d_in[12];
    const float* tw  = (const float*)d_in[13];
    const float* tb  = (const float*)d_in[14];
    float* out = (float*)d_out;

    float *qp, *x, *kp, *vp, *ou, *wqt, *wkt, *wvt, *wot;
    cudaGetSymbolAddress((void**)&qp,  g_qp);
    cudaGetSymbolAddress((void**)&x,   g_x);
    cudaGetSymbolAddress((void**)&kp,  g_kp);
    cudaGetSymbolAddress((void**)&vp,  g_vp);
    cudaGetSymbolAddress((void**)&ou,  g_ou);
    cudaGetSymbolAddress((void**)&wqt, g_wqt);
    cudaGetSymbolAddress((void**)&wkt, g_wkt);
    cudaGetSymbolAddress((void**)&wvt, g_wvt);
    cudaGetSymbolAddress((void**)&wot, g_wot);

    const size_t attn_smem = ATT_SMEM_FLOATS * sizeof(float);
    cudaFuncSetAttribute(attn_kernel,
                         cudaFuncAttributeMaxDynamicSharedMemorySize,
                         (int)attn_smem);
    cudaFuncSetAttribute(gemm_mma,
                         cudaFuncAttributeMaxDynamicSharedMemorySize,
                         GM_SMEM);

    zero_ssq_kernel<<<1, 128>>>();

    // transpose weights: Wt[n,k] = W[k,n]
    dim3 tg(16, 16), tb2(32, 8);
    transpose512<<<tg, tb2>>>(Wq, wqt);
    transpose512<<<tg, tb2>>>(Wk, wkt);
    transpose512<<<tg, tb2>>>(Wv, wvt);
    transpose512<<<tg, tb2>>>(Wo, wot);

    // Q projection: (36864, 512) @ (512, 512)
    gemm_mma<<<dim3(4, 288), 256, GM_SMEM>>>(queries, wqt, bq, qp, BB * NQ, DD, DD);

    // spatial reduction conv + LN
    convln_kernel<<<dim3(256, 16), 256>>>(queries, srw, srb, lng, lnb);

    // K, V projections: (4096, 512) @ (512, 512)
    gemm_mma<<<dim3(4, 32), 256, GM_SMEM>>>(x, wkt, bk, kp, BB * NKK, DD, DD);
    gemm_mma<<<dim3(4, 32), 256, GM_SMEM>>>(x, wvt, bv, vp, BB * NKK, DD, DD);

    vcolsum_kernel<<<BB, 512>>>();

    // fused attention
    attn_kernel<<<dim3(NQ / 16, BB), 256, attn_smem>>>(tw, tb);

    stats_kernel<<<1, 128>>>();

    // normalize (InstanceNorm folded into output)
    norm_kernel<<<(BB * NQ * DD + 255) / 256, 256>>>();

    // output projection -> d_out
    gemm_mma<<<dim3(4, 288), 256, GM_SMEM>>>(ou, wot, bo, out, BB * NQ, DD, DD);
}

// round 6
// speedup vs baseline: 1.8932x; 1.3205x over previous
#include <cuda_runtime.h>
#include <math.h>
#include <cstdint>

// Problem constants
#define BB   16
#define NQ   2304
#define DD   512
#define NH   8
#define DK   64
#define NKK  256
#define HHH  48

// Scratch (device globals; allocation-free per harness rules)
__device__ float g_qp[BB * NQ * DD];     // Q projection
__device__ float g_x [BB * NKK * DD];    // conv+LN output
__device__ float g_kp[BB * NKK * DD];    // K projection
__device__ float g_vp[BB * NKK * DD];    // V projection
__device__ float g_ou[BB * NQ * DD];     // unnormalized attention output
__device__ float g_vs[BB * DD];          // column sums of V per batch
__device__ float g_ssq[BB * NH];         // sum of p^2 per (b,h)
__device__ float g_is [BB * NH];         // 1/sqrt(var+eps) per (b,h)
__device__ float g_wqt[DD * DD];         // transposed weights [N,K]
__device__ float g_wkt[DD * DD];
__device__ float g_wvt[DD * DD];
__device__ float g_wot[DD * DD];

__device__ __forceinline__ uint32_t f2tf32(float f) {
    uint32_t r;
    asm("cvt.rna.tf32.f32 %0, %1;" : "=r"(r) : "f"(f));
    return r;
}
__device__ __forceinline__ void split_tf32(float x, uint32_t& hi, uint32_t& lo) {
    hi = __float_as_uint(x) & 0xffffe000u;
    lo = f2tf32(x - __uint_as_float(hi));
}

__device__ __forceinline__ void mma_16n8k8(
    float* d, const uint32_t* a, const uint32_t* b)
{
    asm volatile(
        "mma.sync.aligned.m16n8k8.row.col.f32.tf32.tf32.f32 "
        "{%0,%1,%2,%3}, {%4,%5,%6,%7}, {%8,%9}, {%0,%1,%2,%3};"
        : "+f"(d[0]), "+f"(d[1]), "+f"(d[2]), "+f"(d[3])
        : "r"(a[0]), "r"(a[1]), "r"(a[2]), "r"(a[3]),
          "r"(b[0]), "r"(b[1]));
}

#define CP_A16(dst, src) \
    asm volatile("cp.async.cg.shared.global [%0], [%1], 16;" \
                 :: "r"(dst), "l"(src))
#define CP_COMMIT() asm volatile("cp.async.commit_group;" ::: "memory")
#define CP_WAIT1()  asm volatile("cp.async.wait_group 1;" ::: "memory")
#define CP_WAIT0()  asm volatile("cp.async.wait_group 0;" ::: "memory")

__device__ __forceinline__ uint32_t smem_u32(const void* p) {
    uint32_t a;
    asm("{ .reg .u64 t; cvta.to.shared.u64 t, %1; cvt.u32.u64 %0, t; }"
        : "=r"(a) : "l"(p));
    return a;
}

// ---------------------------------------------------------------------------
// Warp-MMA 3xTF32 GEMM (fp32 accuracy): C = A(MxK) @ Bt^T + bias.
// Bt is [N,K] row-major. CTA 128x128, BK=32, 8 warps, warp tile 64x32.
// Double-buffered via cp.async.
// ---------------------------------------------------------------------------
#define GM_PAD 36
#define GM_BUF (128 * GM_PAD)            // floats per matrix per buffer
#define GM_SMEM (4 * GM_BUF * 4)         // bytes: 2 bufs x (A,B)

__global__ __launch_bounds__(256, 2) void gemm_mma(
    const float* __restrict__ A, const float* __restrict__ Bt,
    const float* __restrict__ bias, float* __restrict__ C,
    int M, int N, int K)
{
    extern __shared__ float gsm[];
    const int tid  = threadIdx.x;
    const int wid  = tid >> 5, lane = tid & 31;
    const int gid  = lane >> 2, tig = lane & 3;
    const int m_w  = (wid & 1) * 64;
    const int n_w  = (wid >> 1) * 32;
    const int m0   = blockIdx.y * 128;
    const int n0   = blockIdx.x * 128;

    const int lr = tid >> 1;            // 0..127
    const int lc = (tid & 1) * 16;      // 0 or 16
    const uint32_t sbase = smem_u32(gsm);

    float acc[4][4][4];
#pragma unroll
    for (int mi = 0; mi < 4; mi++)
#pragma unroll
        for (int ni = 0; ni < 4; ni++)
#pragma unroll
            for (int r = 0; r < 4; r++) acc[mi][ni][r] = 0.f;

    const int nch = K >> 5;

    auto issue = [&](int c, int buf) {
        const float* Ac = A  + (size_t)(m0 + lr) * K + c * 32 + lc;
        const float* Bc = Bt + (size_t)(n0 + lr) * K + c * 32 + lc;
        uint32_t da = sbase + (uint32_t)(buf * 2 * GM_BUF + lr * GM_PAD + lc) * 4;
        uint32_t db = da + GM_BUF * 4;
#pragma unroll
        for (int j = 0; j < 4; j++) {
            CP_A16(da + j * 16, Ac + j * 4);
            CP_A16(db + j * 16, Bc + j * 4);
        }
    };

    issue(0, 0);
    CP_COMMIT();

    for (int c = 0; c < nch; c++) {
        if (c + 1 < nch) {
            issue(c + 1, (c + 1) & 1);
            CP_COMMIT();
            CP_WAIT1();
        } else {
            CP_WAIT0();
        }
        __syncthreads();

        const float* As = gsm + (c & 1) * 2 * GM_BUF;
        const float* Bs = As + GM_BUF;

#pragma unroll
        for (int ks = 0; ks < 4; ks++) {
            const int kk = ks * 8;
            uint32_t bh[4][2], bl[4][2];
#pragma unroll
            for (int ni = 0; ni < 4; ni++) {
                int r = n_w + ni * 8 + gid;
                split_tf32(Bs[r * GM_PAD + kk + tig],     bh[ni][0], bl[ni][0]);
                split_tf32(Bs[r * GM_PAD + kk + tig + 4], bh[ni][1], bl[ni][1]);
            }
#pragma unroll
            for (int mi = 0; mi < 4; mi++) {
                uint32_t ah[4], al[4];
                int r0 = m_w + mi * 16 + gid;
                split_tf32(As[r0 * GM_PAD + kk + tig],           ah[0], al[0]);
                split_tf32(As[(r0 + 8) * GM_PAD + kk + tig],     ah[1], al[1]);
                split_tf32(As[r0 * GM_PAD + kk + tig + 4],       ah[2], al[2]);
                split_tf32(As[(r0 + 8) * GM_PAD + kk + tig + 4], ah[3], al[3]);
#pragma unroll
                for (int ni = 0; ni < 4; ni++) {
                    mma_16n8k8(acc[mi][ni], al, bh[ni]);
                    mma_16n8k8(acc[mi][ni], ah, bl[ni]);
                    mma_16n8k8(acc[mi][ni], ah, bh[ni]);
                }
            }
        }
        __syncthreads();
    }

    // epilogue + bias
#pragma unroll
    for (int mi = 0; mi < 4; mi++) {
        const int r0 = m0 + m_w + mi * 16 + gid;
        const int r1 = r0 + 8;
#pragma unroll
        for (int ni = 0; ni < 4; ni++) {
            const int col = n0 + n_w + ni * 8 + tig * 2;
            float2 bz = *(const float2*)&bias[col];
            float2 o0 = make_float2(acc[mi][ni][0] + bz.x, acc[mi][ni][1] + bz.y);
            float2 o1 = make_float2(acc[mi][ni][2] + bz.x, acc[mi][ni][3] + bz.y);
            *(float2*)&C[(size_t)r0 * N + col] = o0;
            *(float2*)&C[(size_t)r1 * N + col] = o1;
        }
    }
}

// ---------------------------------------------------------------------------
// 512x512 transpose: Wt[n,k] = W[k,n]
// ---------------------------------------------------------------------------
__global__ void transpose512(const float* __restrict__ W, float* __restrict__ Wt)
{
    __shared__ float t[32][33];
    const int bx = blockIdx.x * 32, by = blockIdx.y * 32;
    const int tx = threadIdx.x, ty = threadIdx.y;   // 32 x 8
#pragma unroll
    for (int i = 0; i < 32; i += 8)
        t[ty + i][tx] = W[(size_t)(by + ty + i) * DD + bx + tx];
    __syncthreads();
#pragma unroll
    for (int i = 0; i < 32; i += 8)
        Wt[(size_t)(bx + ty + i) * DD + by + tx] = t[tx][ty + i];
}

// ---------------------------------------------------------------------------
// Depthwise 4x4 stride-3 conv (pad 1) + LayerNorm over channels.
// ---------------------------------------------------------------------------
__global__ __launch_bounds__(256) void convln_kernel(
    const float* __restrict__ q, const float* __restrict__ srw,
    const float* __restrict__ srb, const float* __restrict__ lng,
    const float* __restrict__ lnb)
{
    const int b  = blockIdx.y;
    const int op = blockIdx.x;
    const int oh = op >> 4, ow = op & 15;
    const int tid = threadIdx.x;
    const int c0 = tid, c1 = tid + 256;

    float a0 = srb[c0], a1 = srb[c1];
#pragma unroll
    for (int kh = 0; kh < 4; kh++) {
        int ih = oh * 3 - 1 + kh;
        if (ih < 0 || ih >= HHH) continue;
#pragma unroll
        for (int kw = 0; kw < 4; kw++) {
            int iw = ow * 3 - 1 + kw;
            if (iw < 0 || iw >= HHH) continue;
            const float* qr = q + ((size_t)b * NQ + ih * HHH + iw) * DD;
            a0 += srw[c0 * 16 + kh * 4 + kw] * qr[c0];
            a1 += srw[c1 * 16 + kh * 4 + kw] * qr[c1];
        }
    }

    float s  = a0 + a1;
    float s2 = a0 * a0 + a1 * a1;
#pragma unroll
    for (int off = 16; off; off >>= 1) {
        s  += __shfl_xor_sync(0xFFFFFFFFu, s,  off);
        s2 += __shfl_xor_sync(0xFFFFFFFFu, s2, off);
    }
    __shared__ float rs[8], rs2[8];
    if ((tid & 31) == 0) { rs[tid >> 5] = s; rs2[tid >> 5] = s2; }
    __syncthreads();
    if (tid == 0) {
        float ts = 0.f, ts2 = 0.f;
#pragma unroll
        for (int i = 0; i < 8; i++) { ts += rs[i]; ts2 += rs2[i]; }
        rs[0] = ts; rs2[0] = ts2;
    }
    __syncthreads();
    const float mu   = rs[0] * (1.f / 512.f);
    const float var  = rs2[0] * (1.f / 512.f) - mu * mu;
    const float rstd = rsqrtf(var + 1e-5f);

    float* xo = g_x + ((size_t)b * NKK + op) * DD;
    xo[c0] = (a0 - mu) * rstd * lng[c0] + lnb[c0];
    xo[c1] = (a1 - mu) * rstd * lng[c1] + lnb[c1];
}

__global__ void vcolsum_kernel()
{
    const int b = blockIdx.x;
    const int c = threadIdx.x;
    float s = 0.f;
    for (int k = 0; k < NKK; k++)
        s += g_vp[((size_t)b * NKK + k) * DD + c];
    g_vs[b * DD + c] = s;
}

__global__ void zero_ssq_kernel()
{
    if (threadIdx.x < BB * NH) g_ssq[threadIdx.x] = 0.f;
}

__global__ void stats_kernel()
{
    const int i = threadIdx.x;
    if (i < BB * NH) {
        const float m = 1.f / 256.f;
        float va = g_ssq[i] / (2304.f * 256.f) - m * m;
        g_is[i] = rsqrtf(va + 1e-5f);
    }
}

__global__ void norm_kernel()
{
    const float m = 1.f / 256.f;
    int idx = blockIdx.x * 256 + threadIdx.x;
    const int total = BB * NQ * DD;
    if (idx < total) {
        int c = idx & 511;
        int b = idx / (NQ * DD);
        int h = c >> 6;
        g_ou[idx] = (g_ou[idx] - m * g_vs[b * DD + c]) * g_is[b * NH + h];
    }
}

// ---------------------------------------------------------------------------
// Fused attention v3: 3xTF32 tensor-core QK + PV.
// Block = (b, 16-query tile), 256 threads, warp = head.
// smem: sc[128][257], qs[16][516], kbuf 2 x [8][516], tw/tb/ssq.
// ---------------------------------------------------------------------------
#define SC_STRIDE 257
#define RW 516
#define KBUF (8 * RW)
#define ATT_SMEM_FLOATS (128 * SC_STRIDE + 16 * RW + 2 * KBUF + 64 + 8 + 8)

__global__ __launch_bounds__(256, 1) void attn_kernel(
    const float* __restrict__ tw, const float* __restrict__ tb)
{
    extern __shared__ float sm[];
    float* sc   = sm;                        // 128 * 257
    float* qs   = sc + 128 * SC_STRIDE;      // 16 * 516
    float* kbuf = qs + 16 * RW;              // 2 * 8 * 516 (K/V chunks)
    float* tws  = kbuf + 2 * KBUF;           // 64
    float* tbs  = tws + 64;                  // 8
    float* ssq  = tbs + 8;                   // 8

    const int tid  = threadIdx.x;
    const int h    = tid >> 5;               // warp = head
    const int lane = tid & 31;
    const int gid  = lane >> 2, tig = lane & 3;
    const int b    = blockIdx.y;
    const int q0   = blockIdx.x * 16;
    const uint32_t kb_addr = smem_u32(kbuf);

    if (tid < 64) tws[tid] = tw[tid];
    if (tid < 8) { tbs[tid] = tb[tid]; ssq[tid] = 0.f; }

    // load Q tile (16 x 512)
    {
        const float* qp = g_qp + ((size_t)b * NQ + q0) * DD;
        for (int idx = tid; idx < 2048; idx += 256) {
            int r = idx >> 7, c4 = (idx & 127) << 2;
            *(float4*)&qs[r * RW + c4] = *(const float4*)&qp[r * DD + c4];
        }
    }
    __syncthreads();

    // Q fragments for this head, split hi/lo (held in registers)
    uint32_t qh[8][4], ql[8][4];
#pragma unroll
    for (int ks = 0; ks < 8; ks++) {
        const float* qb = qs + h * 64 + ks * 8 + tig;
        split_tf32(qb[gid * RW],           qh[ks][0], ql[ks][0]);
        split_tf32(qb[(gid + 8) * RW],     qh[ks][1], ql[ks][1]);
        split_tf32(qb[gid * RW + 4],       qh[ks][2], ql[ks][2]);
        split_tf32(qb[(gid + 8) * RW + 4], qh[ks][3], ql[ks][3]);
    }

    const float* kp = g_kp + (size_t)b * NKK * DD;
    const float* vp = g_vp + (size_t)b * NKK * DD;

    // cp.async one 8-key x 512 chunk into buffer `buf`
    auto issue_chunk = [&](const float* src_base, int chunk, int buf) {
        const float* src = src_base + (size_t)chunk * 8 * DD;
        uint32_t dst = kb_addr + (uint32_t)(buf * KBUF) * 4;
#pragma unroll
        for (int it = 0; it < 4; it++) {
            int idx = tid + it * 256;
            int r = idx >> 7, c4 = (idx & 127) << 2;
            CP_A16(dst + (uint32_t)(r * RW + c4) * 4, src + r * DD + c4);
        }
    };

    // ---- QK: S[q][k] for this head via 3xTF32 MMA ----
    issue_chunk(kp, 0, 0); CP_COMMIT();
    for (int kc = 0; kc < 32; kc++) {
        if (kc + 1 < 32) { issue_chunk(kp, kc + 1, (kc + 1) & 1); CP_COMMIT(); CP_WAIT1(); }
        else CP_WAIT0();
        __syncthreads();
        const float* kt = kbuf + (kc & 1) * KBUF;
        float acc[4] = {0.f, 0.f, 0.f, 0.f};
#pragma unroll
        for (int ks = 0; ks < 8; ks++) {
            uint32_t bh[2], bl[2];
            const float* kr = kt + gid * RW + h * 64 + ks * 8 + tig;
            split_tf32(kr[0], bh[0], bl[0]);
            split_tf32(kr[4], bh[1], bl[1]);
            mma_16n8k8(acc, ql[ks], bh);
            mma_16n8k8(acc, qh[ks], bl);
            mma_16n8k8(acc, qh[ks], bh);
        }
        float* r0 = sc + (gid * 8 + h) * SC_STRIDE + kc * 8 + tig * 2;
        float* r1 = sc + ((gid + 8) * 8 + h) * SC_STRIDE + kc * 8 + tig * 2;
        r0[0] = acc[0] * 0.125f; r0[1] = acc[1] * 0.125f;
        r1[0] = acc[2] * 0.125f; r1[1] = acc[3] * 0.125f;
        __syncthreads();
    }

    // prefetch V chunk 0 (overlaps headmix + softmax)
    issue_chunk(vp, 0, 0); CP_COMMIT();

    // ---- head mixing: s2[o][k] = tb[o] + sum_i tw[o][i]*s[i][k] ----
    {
        const int k = tid;  // 0..255
        for (int q = 0; q < 16; q++) {
            float r[8];
#pragma unroll
            for (int i = 0; i < 8; i++) r[i] = sc[(q * 8 + i) * SC_STRIDE + k];
            float o_[8];
#pragma unroll
            for (int o = 0; o < 8; o++) {
                float s = tbs[o];
#pragma unroll
                for (int i = 0; i < 8; i++) s += tws[o * 8 + i] * r[i];
                o_[o] = s;
            }
#pragma unroll
            for (int o = 0; o < 8; o++) sc[(q * 8 + o) * SC_STRIDE + k] = o_[o];
        }
    }
    __syncthreads();

    // ---- softmax per (q,o) row + sum of squares ----
    if (tid < 128) {
        float* row = sc + tid * SC_STRIDE;
        float mx = -1e30f;
#pragma unroll 4
        for (int k = 0; k < 256; k++) mx = fmaxf(mx, row[k]);
        float s = 0.f;
#pragma unroll 4
        for (int k = 0; k < 256; k++) { float e = expf(row[k] - mx); row[k] = e; s += e; }
        float inv = 1.f / s;
        float lss = 0.f;
#pragma unroll 4
        for (int k = 0; k < 256; k++) { float p = row[k] * inv; row[k] = p; lss += p * p; }
        atomicAdd(&ssq[tid & 7], lss);
    }
    __syncthreads();
    if (tid < 8) atomicAdd(&g_ssq[b * NH + tid], ssq[tid]);

    // ---- P @ V via 3xTF32 MMA ----
    float accj[8][4];
#pragma unroll
    for (int jn = 0; jn < 8; jn++)
#pragma unroll
        for (int r = 0; r < 4; r++) accj[jn][r] = 0.f;

    for (int vc = 0; vc < 32; vc++) {
        if (vc + 1 < 32) { issue_chunk(vp, vc + 1, (vc + 1) & 1); CP_COMMIT(); CP_WAIT1(); }
        else CP_WAIT0();
        __syncthreads();
        const float* vt = kbuf + (vc & 1) * KBUF;

        uint32_t ah[4], al[4];
        const float* pb  = sc + (gid * 8 + h) * SC_STRIDE + vc * 8 + tig;
        const float* pb8 = sc + ((gid + 8) * 8 + h) * SC_STRIDE + vc * 8 + tig;
        split_tf32(pb[0],  ah[0], al[0]);
        split_tf32(pb8[0], ah[1], al[1]);
        split_tf32(pb[4],  ah[2], al[2]);
        split_tf32(pb8[4], ah[3], al[3]);

#pragma unroll
        for (int jn = 0; jn < 8; jn++) {
            uint32_t bh[2], bl[2];
            const float* vr = vt + h * 64 + jn * 8 + gid;
            split_tf32(vr[tig * RW],       bh[0], bl[0]);
            split_tf32(vr[(tig + 4) * RW], bh[1], bl[1]);
            mma_16n8k8(accj[jn], al, bh);
            mma_16n8k8(accj[jn], ah, bl);
            mma_16n8k8(accj[jn], ah, bh);
        }
        __syncthreads();
    }

    // epilogue: thread holds out rows q0+gid, q0+gid+8; cols h*64 + jn*8 + tig*2
#pragma unroll
    for (int jn = 0; jn < 8; jn++) {
        const int col = h * 64 + jn * 8 + tig * 2;
        float* o0 = g_ou + ((size_t)b * NQ + q0 + gid) * DD + col;
        float* o1 = g_ou + ((size_t)b * NQ + q0 + gid + 8) * DD + col;
        *(float2*)o0 = make_float2(accj[jn][0], accj[jn][1]);
        *(float2*)o1 = make_float2(accj[jn][2], accj[jn][3]);
    }
}

// ---------------------------------------------------------------------------
extern "C" void kernel_launch(void* const* d_in, const int* in_sizes, int n_in,
                              void* d_out, int out_size)
{
    (void)in_sizes; (void)n_in; (void)out_size;
    const float* queries = (const float*)d_in[0];
    const float* Wq = (const float*)d_in[1];
    const float* bq = (const float*)d_in[2];
    const float* Wk = (const float*)d_in[3];
    const float* bk = (const float*)d_in[4];
    const float* Wv = (const float*)d_in[5];
    const float* bv = (const float*)d_in[6];
    const float* Wo = (const float*)d_in[7];
    const float* bo = (const float*)d_in[8];
    const float* srw = (const float*)d_in[9];
    const float* srb = (const float*)d_in[10];
    const float* lng = (const float*)d_in[11];
    const float* lnb = (const float*)d_in[12];
    const float* tw  = (const float*)d_in[13];
    const float* tb  = (const float*)d_in[14];
    float* out = (float*)d_out;

    float *qp, *x, *kp, *vp, *ou, *wqt, *wkt, *wvt, *wot;
    cudaGetSymbolAddress((void**)&qp,  g_qp);
    cudaGetSymbolAddress((void**)&x,   g_x);
    cudaGetSymbolAddress((void**)&kp,  g_kp);
    cudaGetSymbolAddress((void**)&vp,  g_vp);
    cudaGetSymbolAddress((void**)&ou,  g_ou);
    cudaGetSymbolAddress((void**)&wqt, g_wqt);
    cudaGetSymbolAddress((void**)&wkt, g_wkt);
    cudaGetSymbolAddress((void**)&wvt, g_wvt);
    cudaGetSymbolAddress((void**)&wot, g_wot);

    const size_t attn_smem = ATT_SMEM_FLOATS * sizeof(float);
    cudaFuncSetAttribute(attn_kernel,
                         cudaFuncAttributeMaxDynamicSharedMemorySize,
                         (int)attn_smem);
    cudaFuncSetAttribute(gemm_mma,
                         cudaFuncAttributeMaxDynamicSharedMemorySize,
                         GM_SMEM);

    zero_ssq_kernel<<<1, 128>>>();

    // transpose weights: Wt[n,k] = W[k,n]
    dim3 tg(16, 16), tb2(32, 8);
    transpose512<<<tg, tb2>>>(Wq, wqt);
    transpose512<<<tg, tb2>>>(Wk, wkt);
    transpose512<<<tg, tb2>>>(Wv, wvt);
    transpose512<<<tg, tb2>>>(Wo, wot);

    // Q projection: (36864, 512) @ (512, 512)
    gemm_mma<<<dim3(4, 288), 256, GM_SMEM>>>(queries, wqt, bq, qp, BB * NQ, DD, DD);

    // spatial reduction conv + LN
    convln_kernel<<<dim3(256, 16), 256>>>(queries, srw, srb, lng, lnb);

    // K, V projections: (4096, 512) @ (512, 512)
    gemm_mma<<<dim3(4, 32), 256, GM_SMEM>>>(x, wkt, bk, kp, BB * NKK, DD, DD);
    gemm_mma<<<dim3(4, 32), 256, GM_SMEM>>>(x, wvt, bv, vp, BB * NKK, DD, DD);

    vcolsum_kernel<<<BB, 512>>>();

    // fused attention
    attn_kernel<<<dim3(NQ / 16, BB), 256, attn_smem>>>(tw, tb);

    stats_kernel<<<1, 128>>>();

    // normalize (InstanceNorm folded into output)
    norm_kernel<<<(BB * NQ * DD + 255) / 256, 256>>>();

    // output projection -> d_out
    gemm_mma<<<dim3(4, 288), 256, GM_SMEM>>>(ou, wot, bo, out, BB * NQ, DD, DD);
}

// round 8
// speedup vs baseline: 2.0826x; 1.1000x over previous
#include <cuda_runtime.h>
#include <cuda_bf16.h>
#include <math.h>
#include <cstdint>

// Problem constants
#define BB   16
#define NQ   2304
#define DD   512
#define NH   8
#define DK   64
#define NKK  256
#define HHH  48

// Scratch (device globals; allocation-free per harness rules)
__device__ float g_qp[BB * NQ * DD];     // Q projection
__device__ float g_x [BB * NKK * DD];    // conv+LN output
__device__ float g_kp[BB * NKK * DD];    // K projection
__device__ float g_vp[BB * NKK * DD];    // V projection
__device__ float g_ou[BB * NQ * DD];     // attention output minus m*vs
__device__ float g_vs[BB * DD];          // column sums of V per batch
__device__ float g_ssq[BB * NH];         // sum of p^2 per (b,h)
__device__ float g_is [BB * NH];         // 1/sqrt(var+eps) per (b,h)
__device__ float g_wqt[DD * DD];         // transposed weights [N,K]
__device__ float g_wkt[DD * DD];
__device__ float g_wvt[DD * DD];
__device__ float g_wot[DD * DD];

__device__ __forceinline__ uint32_t f2tf32(float f) {
    uint32_t r;
    asm("cvt.rna.tf32.f32 %0, %1;" : "=r"(r) : "f"(f));
    return r;
}
__device__ __forceinline__ void split_tf32(float x, uint32_t& hi, uint32_t& lo) {
    hi = __float_as_uint(x) & 0xffffe000u;
    lo = f2tf32(x - __uint_as_float(hi));
}
__device__ __forceinline__ void split_bf16x2(float x0, float x1,
                                             uint32_t& hi, uint32_t& lo) {
    __nv_bfloat162 h = __floats2bfloat162_rn(x0, x1);
    float h0 = __bfloat162float(h.x);
    float h1 = __bfloat162float(h.y);
    __nv_bfloat162 l = __floats2bfloat162_rn(x0 - h0, x1 - h1);
    hi = *reinterpret_cast<uint32_t*>(&h);
    lo = *reinterpret_cast<uint32_t*>(&l);
}

__device__ __forceinline__ void mma_16n8k8(
    float* d, const uint32_t* a, const uint32_t* b)
{
    asm volatile(
        "mma.sync.aligned.m16n8k8.row.col.f32.tf32.tf32.f32 "
        "{%0,%1,%2,%3}, {%4,%5,%6,%7}, {%8,%9}, {%0,%1,%2,%3};"
        : "+f"(d[0]), "+f"(d[1]), "+f"(d[2]), "+f"(d[3])
        : "r"(a[0]), "r"(a[1]), "r"(a[2]), "r"(a[3]),
          "r"(b[0]), "r"(b[1]));
}
__device__ __forceinline__ void mma_bf16_k16(
    float* d, const uint32_t* a, const uint32_t* b)
{
    asm volatile(
        "mma.sync.aligned.m16n8k16.row.col.f32.bf16.bf16.f32 "
        "{%0,%1,%2,%3}, {%4,%5,%6,%7}, {%8,%9}, {%0,%1,%2,%3};"
        : "+f"(d[0]), "+f"(d[1]), "+f"(d[2]), "+f"(d[3])
        : "r"(a[0]), "r"(a[1]), "r"(a[2]), "r"(a[3]),
          "r"(b[0]), "r"(b[1]));
}

#define CP_A16(dst, src) \
    asm volatile("cp.async.cg.shared.global [%0], [%1], 16;" \
                 :: "r"(dst), "l"(src))
#define CP_COMMIT() asm volatile("cp.async.commit_group;" ::: "memory")
#define CP_WAIT1()  asm volatile("cp.async.wait_group 1;" ::: "memory")
#define CP_WAIT0()  asm volatile("cp.async.wait_group 0;" ::: "memory")

__device__ __forceinline__ uint32_t smem_u32(const void* p) {
    uint32_t a;
    asm("{ .reg .u64 t; cvta.to.shared.u64 t, %1; cvt.u32.u64 %0, t; }"
        : "=r"(a) : "l"(p));
    return a;
}

// ---------------------------------------------------------------------------
// Warp-MMA 3xTF32 GEMM (fp32 accuracy): C = A(MxK) @ Bt^T + bias.
// Used for Q and K projections (error-amplified paths).
// ---------------------------------------------------------------------------
#define GM_PAD 36
#define GM_BUF (128 * GM_PAD)
#define GM_SMEM (4 * GM_BUF * 4)

__global__ __launch_bounds__(256, 2) void gemm_mma(
    const float* __restrict__ A, const float* __restrict__ Bt,
    const float* __restrict__ bias, float* __restrict__ C,
    int M, int N, int K)
{
    extern __shared__ float gsm[];
    const int tid  = threadIdx.x;
    const int wid  = tid >> 5, lane = tid & 31;
    const int gid  = lane >> 2, tig = lane & 3;
    const int m_w  = (wid & 1) * 64;
    const int n_w  = (wid >> 1) * 32;
    const int m0   = blockIdx.y * 128;
    const int n0   = blockIdx.x * 128;

    const int lr = tid >> 1;
    const int lc = (tid & 1) * 16;
    const uint32_t sbase = smem_u32(gsm);

    float acc[4][4][4];
#pragma unroll
    for (int mi = 0; mi < 4; mi++)
#pragma unroll
        for (int ni = 0; ni < 4; ni++)
#pragma unroll
            for (int r = 0; r < 4; r++) acc[mi][ni][r] = 0.f;

    const int nch = K >> 5;

    auto issue = [&](int c, int buf) {
        const float* Ac = A  + (size_t)(m0 + lr) * K + c * 32 + lc;
        const float* Bc = Bt + (size_t)(n0 + lr) * K + c * 32 + lc;
        uint32_t da = sbase + (uint32_t)(buf * 2 * GM_BUF + lr * GM_PAD + lc) * 4;
        uint32_t db = da + GM_BUF * 4;
#pragma unroll
        for (int j = 0; j < 4; j++) {
            CP_A16(da + j * 16, Ac + j * 4);
            CP_A16(db + j * 16, Bc + j * 4);
        }
    };

    issue(0, 0);
    CP_COMMIT();

    for (int c = 0; c < nch; c++) {
        if (c + 1 < nch) {
            issue(c + 1, (c + 1) & 1);
            CP_COMMIT();
            CP_WAIT1();
        } else {
            CP_WAIT0();
        }
        __syncthreads();

        const float* As = gsm + (c & 1) * 2 * GM_BUF;
        const float* Bs = As + GM_BUF;

#pragma unroll
        for (int ks = 0; ks < 4; ks++) {
            const int kk = ks * 8;
            uint32_t bh[4][2], bl[4][2];
#pragma unroll
            for (int ni = 0; ni < 4; ni++) {
                int r = n_w + ni * 8 + gid;
                split_tf32(Bs[r * GM_PAD + kk + tig],     bh[ni][0], bl[ni][0]);
                split_tf32(Bs[r * GM_PAD + kk + tig + 4], bh[ni][1], bl[ni][1]);
            }
#pragma unroll
            for (int mi = 0; mi < 4; mi++) {
                uint32_t ah[4], al[4];
                int r0 = m_w + mi * 16 + gid;
                split_tf32(As[r0 * GM_PAD + kk + tig],           ah[0], al[0]);
                split_tf32(As[(r0 + 8) * GM_PAD + kk + tig],     ah[1], al[1]);
                split_tf32(As[r0 * GM_PAD + kk + tig + 4],       ah[2], al[2]);
                split_tf32(As[(r0 + 8) * GM_PAD + kk + tig + 4], ah[3], al[3]);
#pragma unroll
                for (int ni = 0; ni < 4; ni++) {
                    mma_16n8k8(acc[mi][ni], al, bh[ni]);
                    mma_16n8k8(acc[mi][ni], ah, bl[ni]);
                    mma_16n8k8(acc[mi][ni], ah, bh[ni]);
                }
            }
        }
        __syncthreads();
    }

#pragma unroll
    for (int mi = 0; mi < 4; mi++) {
        const int r0 = m0 + m_w + mi * 16 + gid;
        const int r1 = r0 + 8;
#pragma unroll
        for (int ni = 0; ni < 4; ni++) {
            const int col = n0 + n_w + ni * 8 + tig * 2;
            float2 bz = *(const float2*)&bias[col];
            float2 o0 = make_float2(acc[mi][ni][0] + bz.x, acc[mi][ni][1] + bz.y);
            float2 o1 = make_float2(acc[mi][ni][2] + bz.x, acc[mi][ni][3] + bz.y);
            *(float2*)&C[(size_t)r0 * N + col] = o0;
            *(float2*)&C[(size_t)r1 * N + col] = o1;
        }
    }
}

// ---------------------------------------------------------------------------
// Warp-MMA 3-term bf16 GEMM: C = (A*colscale)(MxK) @ Bt^T + bias.
// Used for V projection (is_all=null) and output projection (is_all=g_is,
// which folds the InstanceNorm scale: A col j scaled by is[b, j>>6]).
// Half the MMA instructions of the tf32 path (m16n8k16).
// ---------------------------------------------------------------------------
__global__ __launch_bounds__(256, 2) void gemm_bf16(
    const float* __restrict__ A, const float* __restrict__ Bt,
    const float* __restrict__ bias, float* __restrict__ C,
    int M, int N, int K, const float* __restrict__ is_all)
{
    extern __shared__ float gsm[];
    const int tid  = threadIdx.x;
    const int wid  = tid >> 5, lane = tid & 31;
    const int gid  = lane >> 2, tig = lane & 3;
    const int m_w  = (wid & 1) * 64;
    const int n_w  = (wid >> 1) * 32;
    const int m0   = blockIdx.y * 128;
    const int n0   = blockIdx.x * 128;

    const int lr = tid >> 1;
    const int lc = (tid & 1) * 16;
    const uint32_t sbase = smem_u32(gsm);

    float acc[4][4][4];
#pragma unroll
    for (int mi = 0; mi < 4; mi++)
#pragma unroll
        for (int ni = 0; ni < 4; ni++)
#pragma unroll
            for (int r = 0; r < 4; r++) acc[mi][ni][r] = 0.f;

    const int nch = K >> 5;

    auto issue = [&](int c, int buf) {
        const float* Ac = A  + (size_t)(m0 + lr) * K + c * 32 + lc;
        const float* Bc = Bt + (size_t)(n0 + lr) * K + c * 32 + lc;
        uint32_t da = sbase + (uint32_t)(buf * 2 * GM_BUF + lr * GM_PAD + lc) * 4;
        uint32_t db = da + GM_BUF * 4;
#pragma unroll
        for (int j = 0; j < 4; j++) {
            CP_A16(da + j * 16, Ac + j * 4);
            CP_A16(db + j * 16, Bc + j * 4);
        }
    };

    issue(0, 0);
    CP_COMMIT();

    for (int c = 0; c < nch; c++) {
        if (c + 1 < nch) {
            issue(c + 1, (c + 1) & 1);
            CP_COMMIT();
            CP_WAIT1();
        } else {
            CP_WAIT0();
        }
        __syncthreads();

        const float* As = gsm + (c & 1) * 2 * GM_BUF;
        const float* Bs = As + GM_BUF;

        // per-chunk uniform InstanceNorm scale: head index = c>>1
        float s_cur = 1.f;
        if (is_all) s_cur = is_all[(m0 / NQ) * NH + (c >> 1)];

#pragma unroll
        for (int ks = 0; ks < 2; ks++) {
            const int kb = ks * 16;
            uint32_t bh[4][2], bl[4][2];
#pragma unroll
            for (int ni = 0; ni < 4; ni++) {
                int r = n_w + ni * 8 + gid;
                float2 v0 = *(const float2*)&Bs[r * GM_PAD + kb + 2 * tig];
                float2 v1 = *(const float2*)&Bs[r * GM_PAD + kb + 2 * tig + 8];
                split_bf16x2(v0.x, v0.y, bh[ni][0], bl[ni][0]);
                split_bf16x2(v1.x, v1.y, bh[ni][1], bl[ni][1]);
            }
#pragma unroll
            for (int mi = 0; mi < 4; mi++) {
                uint32_t ah[4], al[4];
                int r0 = m_w + mi * 16 + gid;
                float2 a0 = *(const float2*)&As[r0 * GM_PAD + kb + 2 * tig];
                float2 a1 = *(const float2*)&As[(r0 + 8) * GM_PAD + kb + 2 * tig];
                float2 a2 = *(const float2*)&As[r0 * GM_PAD + kb + 2 * tig + 8];
                float2 a3 = *(const float2*)&As[(r0 + 8) * GM_PAD + kb + 2 * tig + 8];
                split_bf16x2(a0.x * s_cur, a0.y * s_cur, ah[0], al[0]);
                split_bf16x2(a1.x * s_cur, a1.y * s_cur, ah[1], al[1]);
                split_bf16x2(a2.x * s_cur, a2.y * s_cur, ah[2], al[2]);
                split_bf16x2(a3.x * s_cur, a3.y * s_cur, ah[3], al[3]);
#pragma unroll
                for (int ni = 0; ni < 4; ni++) {
                    mma_bf16_k16(acc[mi][ni], al, bh[ni]);
                    mma_bf16_k16(acc[mi][ni], ah, bl[ni]);
                    mma_bf16_k16(acc[mi][ni], ah, bh[ni]);
                }
            }
        }
        __syncthreads();
    }

#pragma unroll
    for (int mi = 0; mi < 4; mi++) {
        const int r0 = m0 + m_w + mi * 16 + gid;
        const int r1 = r0 + 8;
#pragma unroll
        for (int ni = 0; ni < 4; ni++) {
            const int col = n0 + n_w + ni * 8 + tig * 2;
            float2 bz = *(const float2*)&bias[col];
            float2 o0 = make_float2(acc[mi][ni][0] + bz.x, acc[mi][ni][1] + bz.y);
            float2 o1 = make_float2(acc[mi][ni][2] + bz.x, acc[mi][ni][3] + bz.y);
            *(float2*)&C[(size_t)r0 * N + col] = o0;
            *(float2*)&C[(size_t)r1 * N + col] = o1;
        }
    }
}

// ---------------------------------------------------------------------------
// 4x 512x512 transpose in one launch: Wt[n,k] = W[k,n]
// ---------------------------------------------------------------------------
__global__ void transpose4(
    const float* __restrict__ W0, const float* __restrict__ W1,
    const float* __restrict__ W2, const float* __restrict__ W3,
    float* __restrict__ T0, float* __restrict__ T1,
    float* __restrict__ T2, float* __restrict__ T3)
{
    const float* W; float* T;
    switch (blockIdx.z) {
        case 0: W = W0; T = T0; break;
        case 1: W = W1; T = T1; break;
        case 2: W = W2; T = T2; break;
        default: W = W3; T = T3; break;
    }
    __shared__ float t[32][33];
    const int bx = blockIdx.x * 32, by = blockIdx.y * 32;
    const int tx = threadIdx.x, ty = threadIdx.y;   // 32 x 8
#pragma unroll
    for (int i = 0; i < 32; i += 8)
        t[ty + i][tx] = W[(size_t)(by + ty + i) * DD + bx + tx];
    __syncthreads();
#pragma unroll
    for (int i = 0; i < 32; i += 8)
        T[(size_t)(bx + ty + i) * DD + by + tx] = t[tx][ty + i];
}

// ---------------------------------------------------------------------------
// Depthwise 4x4 stride-3 conv (pad 1) + LayerNorm over channels.
// ---------------------------------------------------------------------------
__global__ __launch_bounds__(256) void convln_kernel(
    const float* __restrict__ q, const float* __restrict__ srw,
    const float* __restrict__ srb, const float* __restrict__ lng,
    const float* __restrict__ lnb)
{
    const int b  = blockIdx.y;
    const int op = blockIdx.x;
    const int oh = op >> 4, ow = op & 15;
    const int tid = threadIdx.x;
    const int c0 = tid, c1 = tid + 256;

    float a0 = srb[c0], a1 = srb[c1];
#pragma unroll
    for (int kh = 0; kh < 4; kh++) {
        int ih = oh * 3 - 1 + kh;
        if (ih < 0 || ih >= HHH) continue;
#pragma unroll
        for (int kw = 0; kw < 4; kw++) {
            int iw = ow * 3 - 1 + kw;
            if (iw < 0 || iw >= HHH) continue;
            const float* qr = q + ((size_t)b * NQ + ih * HHH + iw) * DD;
            a0 += srw[c0 * 16 + kh * 4 + kw] * qr[c0];
            a1 += srw[c1 * 16 + kh * 4 + kw] * qr[c1];
        }
    }

    float s  = a0 + a1;
    float s2 = a0 * a0 + a1 * a1;
#pragma unroll
    for (int off = 16; off; off >>= 1) {
        s  += __shfl_xor_sync(0xFFFFFFFFu, s,  off);
        s2 += __shfl_xor_sync(0xFFFFFFFFu, s2, off);
    }
    __shared__ float rs[8], rs2[8];
    if ((tid & 31) == 0) { rs[tid >> 5] = s; rs2[tid >> 5] = s2; }
    __syncthreads();
    if (tid == 0) {
        float ts = 0.f, ts2 = 0.f;
#pragma unroll
        for (int i = 0; i < 8; i++) { ts += rs[i]; ts2 += rs2[i]; }
        rs[0] = ts; rs2[0] = ts2;
    }
    __syncthreads();
    const float mu   = rs[0] * (1.f / 512.f);
    const float var  = rs2[0] * (1.f / 512.f) - mu * mu;
    const float rstd = rsqrtf(var + 1e-5f);

    float* xo = g_x + ((size_t)b * NKK + op) * DD;
    xo[c0] = (a0 - mu) * rstd * lng[c0] + lnb[c0];
    xo[c1] = (a1 - mu) * rstd * lng[c1] + lnb[c1];
}

__global__ void vcolsum_kernel()
{
    const int b = blockIdx.x;
    const int c = threadIdx.x;
    float s = 0.f;
    for (int k = 0; k < NKK; k++)
        s += g_vp[((size_t)b * NKK + k) * DD + c];
    g_vs[b * DD + c] = s;
}

__global__ void zero_ssq_kernel()
{
    if (threadIdx.x < BB * NH) g_ssq[threadIdx.x] = 0.f;
}

__global__ void stats_kernel()
{
    const int i = threadIdx.x;
    if (i < BB * NH) {
        const float m = 1.f / 256.f;
        float va = g_ssq[i] / (2304.f * 256.f) - m * m;
        g_is[i] = rsqrtf(va + 1e-5f);
    }
}

// ---------------------------------------------------------------------------
// Fused attention v4: 3xTF32 tensor-core QK + PV, 16-key chunks,
// epilogue subtracts m*vs (InstanceNorm mean part).
// Block = (b, 16-query tile), 256 threads, warp = head.
// smem: sc[128][257], kbuf 2 x [16][516] (Q staged in buf1), consts.
// ---------------------------------------------------------------------------
#define SC_STRIDE 257
#define RW 516
#define KB16 (16 * RW)
#define ATT_SMEM_FLOATS (128 * SC_STRIDE + 2 * KB16 + 64 + 8 + 8)

__global__ __launch_bounds__(256, 1) void attn_kernel(
    const float* __restrict__ tw, const float* __restrict__ tb)
{
    extern __shared__ float sm[];
    float* sc   = sm;                        // 128 * 257
    float* kbuf = sc + 128 * SC_STRIDE;      // 2 * 16 * 516
    float* tws  = kbuf + 2 * KB16;           // 64
    float* tbs  = tws + 64;                  // 8
    float* ssq  = tbs + 8;                   // 8

    const int tid  = threadIdx.x;
    const int h    = tid >> 5;               // warp = head
    const int lane = tid & 31;
    const int gid  = lane >> 2, tig = lane & 3;
    const int b    = blockIdx.y;
    const int q0   = blockIdx.x * 16;
    const uint32_t kb_addr = smem_u32(kbuf);

    if (tid < 64) tws[tid] = tw[tid];
    if (tid < 8) { tbs[tid] = tb[tid]; ssq[tid] = 0.f; }

    const float* kp = g_kp + (size_t)b * NKK * DD;
    const float* vp = g_vp + (size_t)b * NKK * DD;
    const float* qp = g_qp + ((size_t)b * NQ + q0) * DD;

    // cp.async one 16-row x 512 chunk into buffer `buf`
    auto issue_rows = [&](const float* src, int buf) {
        uint32_t dst = kb_addr + (uint32_t)(buf * KB16) * 4;
#pragma unroll
        for (int it = 0; it < 8; it++) {
            int idx = tid + it * 256;
            int r = idx >> 7, c4 = (idx & 127) << 2;
            CP_A16(dst + (uint32_t)(r * RW + c4) * 4, src + (size_t)r * DD + c4);
        }
    };

    // stage Q into buf1 and K chunk 0 into buf0 concurrently
    issue_rows(qp, 1);
    issue_rows(kp, 0);
    CP_COMMIT();
    CP_WAIT0();
    __syncthreads();

    // Q fragments for this head, split hi/lo (held in registers)
    uint32_t qh[8][4], ql[8][4];
    {
        const float* qsb = kbuf + KB16;
#pragma unroll
        for (int ks = 0; ks < 8; ks++) {
            const float* qb = qsb + h * 64 + ks * 8 + tig;
            split_tf32(qb[gid * RW],           qh[ks][0], ql[ks][0]);
            split_tf32(qb[(gid + 8) * RW],     qh[ks][1], ql[ks][1]);
            split_tf32(qb[gid * RW + 4],       qh[ks][2], ql[ks][2]);
            split_tf32(qb[(gid + 8) * RW + 4], qh[ks][3], ql[ks][3]);
        }
    }
    __syncthreads();

    // ---- QK: S[q][k] for this head, 16 keys per chunk ----
    for (int kc = 0; kc < 16; kc++) {
        if (kc + 1 < 16) {
            issue_rows(kp + (size_t)(kc + 1) * 16 * DD, (kc + 1) & 1);
            CP_COMMIT(); CP_WAIT1();
        } else CP_WAIT0();
        __syncthreads();
        const float* kt = kbuf + (kc & 1) * KB16;

#pragma unroll
        for (int ni = 0; ni < 2; ni++) {
            float acc[4] = {0.f, 0.f, 0.f, 0.f};
#pragma unroll
            for (int ks = 0; ks < 8; ks++) {
                uint32_t bh[2], bl[2];
                const float* kr = kt + (ni * 8 + gid) * RW + h * 64 + ks * 8 + tig;
                split_tf32(kr[0], bh[0], bl[0]);
                split_tf32(kr[4], bh[1], bl[1]);
                mma_16n8k8(acc, ql[ks], bh);
                mma_16n8k8(acc, qh[ks], bl);
                mma_16n8k8(acc, qh[ks], bh);
            }
            const int kbcol = kc * 16 + ni * 8 + tig * 2;
            float* r0 = sc + (gid * 8 + h) * SC_STRIDE + kbcol;
            float* r1 = sc + ((gid + 8) * 8 + h) * SC_STRIDE + kbcol;
            r0[0] = acc[0] * 0.125f; r0[1] = acc[1] * 0.125f;
            r1[0] = acc[2] * 0.125f; r1[1] = acc[3] * 0.125f;
        }
        __syncthreads();
    }

    // prefetch V chunk 0 (overlaps headmix + softmax)
    issue_rows(vp, 0);
    CP_COMMIT();

    // ---- head mixing: s2[o][k] = tb[o] + sum_i tw[o][i]*s[i][k] ----
    {
        const int k = tid;  // 0..255
        for (int q = 0; q < 16; q++) {
            float r[8];
#pragma unroll
            for (int i = 0; i < 8; i++) r[i] = sc[(q * 8 + i) * SC_STRIDE + k];
            float o_[8];
#pragma unroll
            for (int o = 0; o < 8; o++) {
                float s = tbs[o];
#pragma unroll
                for (int i = 0; i < 8; i++) s += tws[o * 8 + i] * r[i];
                o_[o] = s;
            }
#pragma unroll
            for (int o = 0; o < 8; o++) sc[(q * 8 + o) * SC_STRIDE + k] = o_[o];
        }
    }
    __syncthreads();

    // ---- softmax per (q,o) row + sum of squares ----
    if (tid < 128) {
        float* row = sc + tid * SC_STRIDE;
        float mx = -1e30f;
#pragma unroll 4
        for (int k = 0; k < 256; k++) mx = fmaxf(mx, row[k]);
        float s = 0.f;
#pragma unroll 4
        for (int k = 0; k < 256; k++) { float e = expf(row[k] - mx); row[k] = e; s += e; }
        float inv = 1.f / s;
        float lss = 0.f;
#pragma unroll 4
        for (int k = 0; k < 256; k++) { float p = row[k] * inv; row[k] = p; lss += p * p; }
        atomicAdd(&ssq[tid & 7], lss);
    }
    __syncthreads();
    if (tid < 8) atomicAdd(&g_ssq[b * NH + tid], ssq[tid]);

    // ---- P @ V, 16 keys per chunk (two k8 substeps) ----
    float accj[8][4];
#pragma unroll
    for (int jn = 0; jn < 8; jn++)
#pragma unroll
        for (int r = 0; r < 4; r++) accj[jn][r] = 0.f;

    for (int vc = 0; vc < 16; vc++) {
        if (vc + 1 < 16) {
            issue_rows(vp + (size_t)(vc + 1) * 16 * DD, (vc + 1) & 1);
            CP_COMMIT(); CP_WAIT1();
        } else CP_WAIT0();
        __syncthreads();
        const float* vt = kbuf + (vc & 1) * KB16;

#pragma unroll
        for (int ksub = 0; ksub < 2; ksub++) {
            uint32_t ah[4], al[4];
            const int kcol = vc * 16 + ksub * 8 + tig;
            const float* pb  = sc + (gid * 8 + h) * SC_STRIDE + kcol;
            const float* pb8 = sc + ((gid + 8) * 8 + h) * SC_STRIDE + kcol;
            split_tf32(pb[0],  ah[0], al[0]);
            split_tf32(pb8[0], ah[1], al[1]);
            split_tf32(pb[4],  ah[2], al[2]);
            split_tf32(pb8[4], ah[3], al[3]);

#pragma unroll
            for (int jn = 0; jn < 8; jn++) {
                uint32_t bh[2], bl[2];
                const float* vr = vt + h * 64 + jn * 8 + gid;
                split_tf32(vr[(ksub * 8 + tig) * RW],       bh[0], bl[0]);
                split_tf32(vr[(ksub * 8 + tig + 4) * RW],   bh[1], bl[1]);
                mma_16n8k8(accj[jn], al, bh);
                mma_16n8k8(accj[jn], ah, bl);
                mma_16n8k8(accj[jn], ah, bh);
            }
        }
        __syncthreads();
    }

    // epilogue: subtract m*vs (InstanceNorm mean part), write g_ou
    const float m256 = 1.f / 256.f;
#pragma unroll
    for (int jn = 0; jn < 8; jn++) {
        const int col = h * 64 + jn * 8 + tig * 2;
        float2 vsv = *(const float2*)&g_vs[b * DD + col];
        float* o0 = g_ou + ((size_t)b * NQ + q0 + gid) * DD + col;
        float* o1 = g_ou + ((size_t)b * NQ + q0 + gid + 8) * DD + col;
        *(float2*)o0 = make_float2(accj[jn][0] - m256 * vsv.x,
                                   accj[jn][1] - m256 * vsv.y);
        *(float2*)o1 = make_float2(accj[jn][2] - m256 * vsv.x,
                                   accj[jn][3] - m256 * vsv.y);
    }
}

// ---------------------------------------------------------------------------
extern "C" void kernel_launch(void* const* d_in, const int* in_sizes, int n_in,
                              void* d_out, int out_size)
{
    (void)in_sizes; (void)n_in; (void)out_size;
    const float* queries = (const float*)d_in[0];
    const float* Wq = (const float*)d_in[1];
    const float* bq = (const float*)d_in[2];
    const float* Wk = (const float*)d_in[3];
    const float* bk = (const float*)d_in[4];
    const float* Wv = (const float*)d_in[5];
    const float* bv = (const float*)d_in[6];
    const float* Wo = (const float*)d_in[7];
    const float* bo = (const float*)d_in[8];
    const float* srw = (const float*)d_in[9];
    const float* srb = (const float*)d_in[10];
    const float* lng = (const float*)d_in[11];
    const float* lnb = (const float*)d_in[12];
    const float* tw  = (const float*)d_in[13];
    const float* tb  = (const float*)d_in[14];
    float* out = (float*)d_out;

    float *qp, *x, *kp, *vp, *ou, *wqt, *wkt, *wvt, *wot, *isp;
    cudaGetSymbolAddress((void**)&qp,  g_qp);
    cudaGetSymbolAddress((void**)&x,   g_x);
    cudaGetSymbolAddress((void**)&kp,  g_kp);
    cudaGetSymbolAddress((void**)&vp,  g_vp);
    cudaGetSymbolAddress((void**)&ou,  g_ou);
    cudaGetSymbolAddress((void**)&wqt, g_wqt);
    cudaGetSymbolAddress((void**)&wkt, g_wkt);
    cudaGetSymbolAddress((void**)&wvt, g_wvt);
    cudaGetSymbolAddress((void**)&wot, g_wot);
    cudaGetSymbolAddress((void**)&isp, g_is);

    const size_t attn_smem = ATT_SMEM_FLOATS * sizeof(float);
    cudaFuncSetAttribute(attn_kernel,
                         cudaFuncAttributeMaxDynamicSharedMemorySize,
                         (int)attn_smem);
    cudaFuncSetAttribute(gemm_mma,
                         cudaFuncAttributeMaxDynamicSharedMemorySize,
                         GM_SMEM);
    cudaFuncSetAttribute(gemm_bf16,
                         cudaFuncAttributeMaxDynamicSharedMemorySize,
                         GM_SMEM);

    zero_ssq_kernel<<<1, 128>>>();

    // transpose all 4 weights in one launch
    transpose4<<<dim3(16, 16, 4), dim3(32, 8)>>>(Wq, Wk, Wv, Wo,
                                                 wqt, wkt, wvt, wot);

    // Q projection (amplified path: 3xTF32)
    gemm_mma<<<dim3(4, 288), 256, GM_SMEM>>>(queries, wqt, bq, qp, BB * NQ, DD, DD);

    // spatial reduction conv + LN
    convln_kernel<<<dim3(256, 16), 256>>>(queries, srw, srb, lng, lnb);

    // K projection (amplified path: 3xTF32)
    gemm_mma<<<dim3(4, 32), 256, GM_SMEM>>>(x, wkt, bk, kp, BB * NKK, DD, DD);
    // V projection (safe path: bf16x3)
    gemm_bf16<<<dim3(4, 32), 256, GM_SMEM>>>(x, wvt, bv, vp, BB * NKK, DD, DD, nullptr);

    vcolsum_kernel<<<BB, 512>>>();

    // fused attention (epilogue includes -m*vs)
    attn_kernel<<<dim3(NQ / 16, BB), 256, attn_smem>>>(tw, tb);

    stats_kernel<<<1, 128>>>();

    // output projection with fused InstanceNorm scale (safe path: bf16x3)
    gemm_bf16<<<dim3(4, 288), 256, GM_SMEM>>>(ou, wot, bo, out, BB * NQ, DD, DD, isp);
}

// round 9
// speedup vs baseline: 2.2607x; 1.0855x over previous
#include <cuda_runtime.h>
#include <cuda_bf16.h>
#include <math.h>
#include <cstdint>

// Problem constants
#define BB   16
#define NQ   2304
#define DD   512
#define NH   8
#define DK   64
#define NKK  256
#define HHH  48

// Scratch (device globals; allocation-free per harness rules)
__device__ float g_qp[BB * NQ * DD];     // Q projection
__device__ float g_x [BB * NKK * DD];    // conv+LN output
__device__ float g_kp[BB * NKK * DD];    // K projection
__device__ float g_vp[BB * NKK * DD];    // V projection
__device__ float g_ou[BB * NQ * DD];     // (p-m) @ V
__device__ float g_ssq[BB * NH];         // sum of p^2 per (b,h)
__device__ float g_is [BB * NH];         // 1/sqrt(var+eps) per (b,h)
__device__ float g_wqt[DD * DD];         // transposed weights [N,K]
__device__ float g_wkt[DD * DD];
__device__ float g_wvt[DD * DD];
__device__ float g_wot[DD * DD];

__device__ __forceinline__ uint32_t f2tf32(float f) {
    uint32_t r;
    asm("cvt.rna.tf32.f32 %0, %1;" : "=r"(r) : "f"(f));
    return r;
}
__device__ __forceinline__ void split_tf32(float x, uint32_t& hi, uint32_t& lo) {
    hi = __float_as_uint(x) & 0xffffe000u;
    lo = f2tf32(x - __uint_as_float(hi));
}
__device__ __forceinline__ void split_bf16x2(float x0, float x1,
                                             uint32_t& hi, uint32_t& lo) {
    __nv_bfloat162 h = __floats2bfloat162_rn(x0, x1);
    float h0 = __bfloat162float(h.x);
    float h1 = __bfloat162float(h.y);
    __nv_bfloat162 l = __floats2bfloat162_rn(x0 - h0, x1 - h1);
    hi = *reinterpret_cast<uint32_t*>(&h);
    lo = *reinterpret_cast<uint32_t*>(&l);
}

__device__ __forceinline__ void mma_16n8k8(
    float* d, const uint32_t* a, const uint32_t* b)
{
    asm volatile(
        "mma.sync.aligned.m16n8k8.row.col.f32.tf32.tf32.f32 "
        "{%0,%1,%2,%3}, {%4,%5,%6,%7}, {%8,%9}, {%0,%1,%2,%3};"
        : "+f"(d[0]), "+f"(d[1]), "+f"(d[2]), "+f"(d[3])
        : "r"(a[0]), "r"(a[1]), "r"(a[2]), "r"(a[3]),
          "r"(b[0]), "r"(b[1]));
}
__device__ __forceinline__ void mma_bf16_k16(
    float* d, const uint32_t* a, const uint32_t* b)
{
    asm volatile(
        "mma.sync.aligned.m16n8k16.row.col.f32.bf16.bf16.f32 "
        "{%0,%1,%2,%3}, {%4,%5,%6,%7}, {%8,%9}, {%0,%1,%2,%3};"
        : "+f"(d[0]), "+f"(d[1]), "+f"(d[2]), "+f"(d[3])
        : "r"(a[0]), "r"(a[1]), "r"(a[2]), "r"(a[3]),
          "r"(b[0]), "r"(b[1]));
}

#define CP_A16(dst, src) \
    asm volatile("cp.async.cg.shared.global [%0], [%1], 16;" \
                 :: "r"(dst), "l"(src))
#define CP_COMMIT() asm volatile("cp.async.commit_group;" ::: "memory")
#define CP_WAIT1()  asm volatile("cp.async.wait_group 1;" ::: "memory")
#define CP_WAIT0()  asm volatile("cp.async.wait_group 0;" ::: "memory")

__device__ __forceinline__ uint32_t smem_u32(const void* p) {
    uint32_t a;
    asm("{ .reg .u64 t; cvta.to.shared.u64 t, %1; cvt.u32.u64 %0, t; }"
        : "=r"(a) : "l"(p));
    return a;
}

// ---------------------------------------------------------------------------
// Warp-MMA 3xTF32 GEMM (fp32 accuracy): C = A(MxK) @ Bt^T + bias.
// Used for Q and K projections (error-amplified paths).
// ---------------------------------------------------------------------------
#define GM_PAD 36
#define GM_BUF (128 * GM_PAD)
#define GM_SMEM (4 * GM_BUF * 4)

__global__ __launch_bounds__(256, 2) void gemm_mma(
    const float* __restrict__ A, const float* __restrict__ Bt,
    const float* __restrict__ bias, float* __restrict__ C,
    int M, int N, int K)
{
    extern __shared__ float gsm[];
    const int tid  = threadIdx.x;
    const int wid  = tid >> 5, lane = tid & 31;
    const int gid  = lane >> 2, tig = lane & 3;
    const int m_w  = (wid & 1) * 64;
    const int n_w  = (wid >> 1) * 32;
    const int m0   = blockIdx.y * 128;
    const int n0   = blockIdx.x * 128;

    const int lr = tid >> 1;
    const int lc = (tid & 1) * 16;
    const uint32_t sbase = smem_u32(gsm);

    float acc[4][4][4];
#pragma unroll
    for (int mi = 0; mi < 4; mi++)
#pragma unroll
        for (int ni = 0; ni < 4; ni++)
#pragma unroll
            for (int r = 0; r < 4; r++) acc[mi][ni][r] = 0.f;

    const int nch = K >> 5;

    auto issue = [&](int c, int buf) {
        const float* Ac = A  + (size_t)(m0 + lr) * K + c * 32 + lc;
        const float* Bc = Bt + (size_t)(n0 + lr) * K + c * 32 + lc;
        uint32_t da = sbase + (uint32_t)(buf * 2 * GM_BUF + lr * GM_PAD + lc) * 4;
        uint32_t db = da + GM_BUF * 4;
#pragma unroll
        for (int j = 0; j < 4; j++) {
            CP_A16(da + j * 16, Ac + j * 4);
            CP_A16(db + j * 16, Bc + j * 4);
        }
    };

    issue(0, 0);
    CP_COMMIT();

    for (int c = 0; c < nch; c++) {
        if (c + 1 < nch) {
            issue(c + 1, (c + 1) & 1);
            CP_COMMIT();
            CP_WAIT1();
        } else {
            CP_WAIT0();
        }
        __syncthreads();

        const float* As = gsm + (c & 1) * 2 * GM_BUF;
        const float* Bs = As + GM_BUF;

#pragma unroll
        for (int ks = 0; ks < 4; ks++) {
            const int kk = ks * 8;
            uint32_t bh[4][2], bl[4][2];
#pragma unroll
            for (int ni = 0; ni < 4; ni++) {
                int r = n_w + ni * 8 + gid;
                split_tf32(Bs[r * GM_PAD + kk + tig],     bh[ni][0], bl[ni][0]);
                split_tf32(Bs[r * GM_PAD + kk + tig + 4], bh[ni][1], bl[ni][1]);
            }
#pragma unroll
            for (int mi = 0; mi < 4; mi++) {
                uint32_t ah[4], al[4];
                int r0 = m_w + mi * 16 + gid;
                split_tf32(As[r0 * GM_PAD + kk + tig],           ah[0], al[0]);
                split_tf32(As[(r0 + 8) * GM_PAD + kk + tig],     ah[1], al[1]);
                split_tf32(As[r0 * GM_PAD + kk + tig + 4],       ah[2], al[2]);
                split_tf32(As[(r0 + 8) * GM_PAD + kk + tig + 4], ah[3], al[3]);
#pragma unroll
                for (int ni = 0; ni < 4; ni++) {
                    mma_16n8k8(acc[mi][ni], al, bh[ni]);
                    mma_16n8k8(acc[mi][ni], ah, bl[ni]);
                    mma_16n8k8(acc[mi][ni], ah, bh[ni]);
                }
            }
        }
        __syncthreads();
    }

#pragma unroll
    for (int mi = 0; mi < 4; mi++) {
        const int r0 = m0 + m_w + mi * 16 + gid;
        const int r1 = r0 + 8;
#pragma unroll
        for (int ni = 0; ni < 4; ni++) {
            const int col = n0 + n_w + ni * 8 + tig * 2;
            float2 bz = *(const float2*)&bias[col];
            float2 o0 = make_float2(acc[mi][ni][0] + bz.x, acc[mi][ni][1] + bz.y);
            float2 o1 = make_float2(acc[mi][ni][2] + bz.x, acc[mi][ni][3] + bz.y);
            *(float2*)&C[(size_t)r0 * N + col] = o0;
            *(float2*)&C[(size_t)r1 * N + col] = o1;
        }
    }
}

// ---------------------------------------------------------------------------
// Warp-MMA 3-term bf16 GEMM: C = (A*colscale)(MxK) @ Bt^T + bias.
// Used for V projection (is_all=null) and output projection (is_all=g_is).
// ---------------------------------------------------------------------------
__global__ __launch_bounds__(256, 2) void gemm_bf16(
    const float* __restrict__ A, const float* __restrict__ Bt,
    const float* __restrict__ bias, float* __restrict__ C,
    int M, int N, int K, const float* __restrict__ is_all)
{
    extern __shared__ float gsm[];
    const int tid  = threadIdx.x;
    const int wid  = tid >> 5, lane = tid & 31;
    const int gid  = lane >> 2, tig = lane & 3;
    const int m_w  = (wid & 1) * 64;
    const int n_w  = (wid >> 1) * 32;
    const int m0   = blockIdx.y * 128;
    const int n0   = blockIdx.x * 128;

    const int lr = tid >> 1;
    const int lc = (tid & 1) * 16;
    const uint32_t sbase = smem_u32(gsm);

    float acc[4][4][4];
#pragma unroll
    for (int mi = 0; mi < 4; mi++)
#pragma unroll
        for (int ni = 0; ni < 4; ni++)
#pragma unroll
            for (int r = 0; r < 4; r++) acc[mi][ni][r] = 0.f;

    const int nch = K >> 5;

    auto issue = [&](int c, int buf) {
        const float* Ac = A  + (size_t)(m0 + lr) * K + c * 32 + lc;
        const float* Bc = Bt + (size_t)(n0 + lr) * K + c * 32 + lc;
        uint32_t da = sbase + (uint32_t)(buf * 2 * GM_BUF + lr * GM_PAD + lc) * 4;
        uint32_t db = da + GM_BUF * 4;
#pragma unroll
        for (int j = 0; j < 4; j++) {
            CP_A16(da + j * 16, Ac + j * 4);
            CP_A16(db + j * 16, Bc + j * 4);
        }
    };

    issue(0, 0);
    CP_COMMIT();

    for (int c = 0; c < nch; c++) {
        if (c + 1 < nch) {
            issue(c + 1, (c + 1) & 1);
            CP_COMMIT();
            CP_WAIT1();
        } else {
            CP_WAIT0();
        }
        __syncthreads();

        const float* As = gsm + (c & 1) * 2 * GM_BUF;
        const float* Bs = As + GM_BUF;

        // per-chunk uniform InstanceNorm scale: head index = c>>1
        float s_cur = 1.f;
        if (is_all) s_cur = is_all[(m0 / NQ) * NH + (c >> 1)];

#pragma unroll
        for (int ks = 0; ks < 2; ks++) {
            const int kb = ks * 16;
            uint32_t bh[4][2], bl[4][2];
#pragma unroll
            for (int ni = 0; ni < 4; ni++) {
                int r = n_w + ni * 8 + gid;
                float2 v0 = *(const float2*)&Bs[r * GM_PAD + kb + 2 * tig];
                float2 v1 = *(const float2*)&Bs[r * GM_PAD + kb + 2 * tig + 8];
                split_bf16x2(v0.x, v0.y, bh[ni][0], bl[ni][0]);
                split_bf16x2(v1.x, v1.y, bh[ni][1], bl[ni][1]);
            }
#pragma unroll
            for (int mi = 0; mi < 4; mi++) {
                uint32_t ah[4], al[4];
                int r0 = m_w + mi * 16 + gid;
                float2 a0 = *(const float2*)&As[r0 * GM_PAD + kb + 2 * tig];
                float2 a1 = *(const float2*)&As[(r0 + 8) * GM_PAD + kb + 2 * tig];
                float2 a2 = *(const float2*)&As[r0 * GM_PAD + kb + 2 * tig + 8];
                float2 a3 = *(const float2*)&As[(r0 + 8) * GM_PAD + kb + 2 * tig + 8];
                split_bf16x2(a0.x * s_cur, a0.y * s_cur, ah[0], al[0]);
                split_bf16x2(a1.x * s_cur, a1.y * s_cur, ah[1], al[1]);
                split_bf16x2(a2.x * s_cur, a2.y * s_cur, ah[2], al[2]);
                split_bf16x2(a3.x * s_cur, a3.y * s_cur, ah[3], al[3]);
#pragma unroll
                for (int ni = 0; ni < 4; ni++) {
                    mma_bf16_k16(acc[mi][ni], al, bh[ni]);
                    mma_bf16_k16(acc[mi][ni], ah, bl[ni]);
                    mma_bf16_k16(acc[mi][ni], ah, bh[ni]);
                }
            }
        }
        __syncthreads();
    }

#pragma unroll
    for (int mi = 0; mi < 4; mi++) {
        const int r0 = m0 + m_w + mi * 16 + gid;
        const int r1 = r0 + 8;
#pragma unroll
        for (int ni = 0; ni < 4; ni++) {
            const int col = n0 + n_w + ni * 8 + tig * 2;
            float2 bz = *(const float2*)&bias[col];
            float2 o0 = make_float2(acc[mi][ni][0] + bz.x, acc[mi][ni][1] + bz.y);
            float2 o1 = make_float2(acc[mi][ni][2] + bz.x, acc[mi][ni][3] + bz.y);
            *(float2*)&C[(size_t)r0 * N + col] = o0;
            *(float2*)&C[(size_t)r1 * N + col] = o1;
        }
    }
}

// ---------------------------------------------------------------------------
// 4x 512x512 transpose in one launch: Wt[n,k] = W[k,n]
// ---------------------------------------------------------------------------
__global__ void transpose4(
    const float* __restrict__ W0, const float* __restrict__ W1,
    const float* __restrict__ W2, const float* __restrict__ W3,
    float* __restrict__ T0, float* __restrict__ T1,
    float* __restrict__ T2, float* __restrict__ T3)
{
    const float* W; float* T;
    switch (blockIdx.z) {
        case 0: W = W0; T = T0; break;
        case 1: W = W1; T = T1; break;
        case 2: W = W2; T = T2; break;
        default: W = W3; T = T3; break;
    }
    __shared__ float t[32][33];
    const int bx = blockIdx.x * 32, by = blockIdx.y * 32;
    const int tx = threadIdx.x, ty = threadIdx.y;   // 32 x 8
#pragma unroll
    for (int i = 0; i < 32; i += 8)
        t[ty + i][tx] = W[(size_t)(by + ty + i) * DD + bx + tx];
    __syncthreads();
#pragma unroll
    for (int i = 0; i < 32; i += 8)
        T[(size_t)(bx + ty + i) * DD + by + tx] = t[tx][ty + i];
}

// ---------------------------------------------------------------------------
// Depthwise 4x4 stride-3 conv (pad 1) + LayerNorm over channels.
// ---------------------------------------------------------------------------
__global__ __launch_bounds__(256) void convln_kernel(
    const float* __restrict__ q, const float* __restrict__ srw,
    const float* __restrict__ srb, const float* __restrict__ lng,
    const float* __restrict__ lnb)
{
    const int b  = blockIdx.y;
    const int op = blockIdx.x;
    const int oh = op >> 4, ow = op & 15;
    const int tid = threadIdx.x;
    const int c0 = tid, c1 = tid + 256;

    float a0 = srb[c0], a1 = srb[c1];
#pragma unroll
    for (int kh = 0; kh < 4; kh++) {
        int ih = oh * 3 - 1 + kh;
        if (ih < 0 || ih >= HHH) continue;
#pragma unroll
        for (int kw = 0; kw < 4; kw++) {
            int iw = ow * 3 - 1 + kw;
            if (iw < 0 || iw >= HHH) continue;
            const float* qr = q + ((size_t)b * NQ + ih * HHH + iw) * DD;
            a0 += srw[c0 * 16 + kh * 4 + kw] * qr[c0];
            a1 += srw[c1 * 16 + kh * 4 + kw] * qr[c1];
        }
    }

    float s  = a0 + a1;
    float s2 = a0 * a0 + a1 * a1;
#pragma unroll
    for (int off = 16; off; off >>= 1) {
        s  += __shfl_xor_sync(0xFFFFFFFFu, s,  off);
        s2 += __shfl_xor_sync(0xFFFFFFFFu, s2, off);
    }
    __shared__ float rs[8], rs2[8];
    if ((tid & 31) == 0) { rs[tid >> 5] = s; rs2[tid >> 5] = s2; }
    __syncthreads();
    if (tid == 0) {
        float ts = 0.f, ts2 = 0.f;
#pragma unroll
        for (int i = 0; i < 8; i++) { ts += rs[i]; ts2 += rs2[i]; }
        rs[0] = ts; rs2[0] = ts2;
    }
    __syncthreads();
    const float mu   = rs[0] * (1.f / 512.f);
    const float var  = rs2[0] * (1.f / 512.f) - mu * mu;
    const float rstd = rsqrtf(var + 1e-5f);

    float* xo = g_x + ((size_t)b * NKK + op) * DD;
    xo[c0] = (a0 - mu) * rstd * lng[c0] + lnb[c0];
    xo[c1] = (a1 - mu) * rstd * lng[c1] + lnb[c1];
}

__global__ void zero_ssq_kernel()
{
    if (threadIdx.x < BB * NH) g_ssq[threadIdx.x] = 0.f;
}

__global__ void stats_kernel()
{
    const int i = threadIdx.x;
    if (i < BB * NH) {
        const float m = 1.f / 256.f;
        float va = g_ssq[i] / (2304.f * 256.f) - m * m;
        g_is[i] = rsqrtf(va + 1e-5f);
    }
}

// ---------------------------------------------------------------------------
// Fused attention v5: 3xTF32 QK, (p-m) stored by softmax, bf16x3 k16 PV.
// Block = (b, 16-query tile), 256 threads, warp = head.
// smem: sc[128][257], kbuf 2 x [16][516] (Q staged in buf1), consts.
// ---------------------------------------------------------------------------
#define SC_STRIDE 257
#define RW 516
#define KB16 (16 * RW)
#define ATT_SMEM_FLOATS (128 * SC_STRIDE + 2 * KB16 + 64 + 8 + 8)

__global__ __launch_bounds__(256, 1) void attn_kernel(
    const float* __restrict__ tw, const float* __restrict__ tb)
{
    extern __shared__ float sm[];
    float* sc   = sm;                        // 128 * 257
    float* kbuf = sc + 128 * SC_STRIDE;      // 2 * 16 * 516
    float* tws  = kbuf + 2 * KB16;           // 64
    float* tbs  = tws + 64;                  // 8
    float* ssq  = tbs + 8;                   // 8

    const int tid  = threadIdx.x;
    const int h    = tid >> 5;               // warp = head
    const int lane = tid & 31;
    const int gid  = lane >> 2, tig = lane & 3;
    const int b    = blockIdx.y;
    const int q0   = blockIdx.x * 16;
    const uint32_t kb_addr = smem_u32(kbuf);

    if (tid < 64) tws[tid] = tw[tid];
    if (tid < 8) { tbs[tid] = tb[tid]; ssq[tid] = 0.f; }

    const float* kp = g_kp + (size_t)b * NKK * DD;
    const float* vp = g_vp + (size_t)b * NKK * DD;
    const float* qp = g_qp + ((size_t)b * NQ + q0) * DD;

    // cp.async one 16-row x 512 chunk into buffer `buf`
    auto issue_rows = [&](const float* src, int buf) {
        uint32_t dst = kb_addr + (uint32_t)(buf * KB16) * 4;
#pragma unroll
        for (int it = 0; it < 8; it++) {
            int idx = tid + it * 256;
            int r = idx >> 7, c4 = (idx & 127) << 2;
            CP_A16(dst + (uint32_t)(r * RW + c4) * 4, src + (size_t)r * DD + c4);
        }
    };

    // stage Q into buf1 and K chunk 0 into buf0 concurrently
    issue_rows(qp, 1);
    issue_rows(kp, 0);
    CP_COMMIT();
    CP_WAIT0();
    __syncthreads();

    // Q fragments for this head, split hi/lo (held in registers)
    uint32_t qh[8][4], ql[8][4];
    {
        const float* qsb = kbuf + KB16;
#pragma unroll
        for (int ks = 0; ks < 8; ks++) {
            const float* qb = qsb + h * 64 + ks * 8 + tig;
            split_tf32(qb[gid * RW],           qh[ks][0], ql[ks][0]);
            split_tf32(qb[(gid + 8) * RW],     qh[ks][1], ql[ks][1]);
            split_tf32(qb[gid * RW + 4],       qh[ks][2], ql[ks][2]);
            split_tf32(qb[(gid + 8) * RW + 4], qh[ks][3], ql[ks][3]);
        }
    }
    __syncthreads();

    // ---- QK: S[q][k] for this head, 16 keys per chunk (3xTF32) ----
    for (int kc = 0; kc < 16; kc++) {
        if (kc + 1 < 16) {
            issue_rows(kp + (size_t)(kc + 1) * 16 * DD, (kc + 1) & 1);
            CP_COMMIT(); CP_WAIT1();
        } else CP_WAIT0();
        __syncthreads();
        const float* kt = kbuf + (kc & 1) * KB16;

#pragma unroll
        for (int ni = 0; ni < 2; ni++) {
            float acc[4] = {0.f, 0.f, 0.f, 0.f};
#pragma unroll
            for (int ks = 0; ks < 8; ks++) {
                uint32_t bh[2], bl[2];
                const float* kr = kt + (ni * 8 + gid) * RW + h * 64 + ks * 8 + tig;
                split_tf32(kr[0], bh[0], bl[0]);
                split_tf32(kr[4], bh[1], bl[1]);
                mma_16n8k8(acc, ql[ks], bh);
                mma_16n8k8(acc, qh[ks], bl);
                mma_16n8k8(acc, qh[ks], bh);
            }
            const int kbcol = kc * 16 + ni * 8 + tig * 2;
            float* r0 = sc + (gid * 8 + h) * SC_STRIDE + kbcol;
            float* r1 = sc + ((gid + 8) * 8 + h) * SC_STRIDE + kbcol;
            r0[0] = acc[0] * 0.125f; r0[1] = acc[1] * 0.125f;
            r1[0] = acc[2] * 0.125f; r1[1] = acc[3] * 0.125f;
        }
        __syncthreads();
    }

    // prefetch V chunk 0 (overlaps headmix + softmax)
    issue_rows(vp, 0);
    CP_COMMIT();

    // ---- head mixing: s2[o][k] = tb[o] + sum_i tw[o][i]*s[i][k] ----
    {
        const int k = tid;  // 0..255
        for (int q = 0; q < 16; q++) {
            float r[8];
#pragma unroll
            for (int i = 0; i < 8; i++) r[i] = sc[(q * 8 + i) * SC_STRIDE + k];
            float o_[8];
#pragma unroll
            for (int o = 0; o < 8; o++) {
                float s = tbs[o];
#pragma unroll
                for (int i = 0; i < 8; i++) s += tws[o * 8 + i] * r[i];
                o_[o] = s;
            }
#pragma unroll
            for (int o = 0; o < 8; o++) sc[(q * 8 + o) * SC_STRIDE + k] = o_[o];
        }
    }
    __syncthreads();

    // ---- softmax per (q,o) row: all 256 threads, 2 per row ----
    // writes (p - 1/256) back; accumulates sum p^2
    {
        const float m256 = 1.f / 256.f;
        const int row_i = tid >> 1;          // 0..127
        const int half  = tid & 1;
        float* row = sc + row_i * SC_STRIDE + half * 128;
        float mx = -1e30f;
#pragma unroll 4
        for (int k = 0; k < 128; k++) mx = fmaxf(mx, row[k]);
        mx = fmaxf(mx, __shfl_xor_sync(0xFFFFFFFFu, mx, 1));
        float s = 0.f;
#pragma unroll 4
        for (int k = 0; k < 128; k++) { float e = expf(row[k] - mx); row[k] = e; s += e; }
        s += __shfl_xor_sync(0xFFFFFFFFu, s, 1);
        float inv = 1.f / s;
        float lss = 0.f;
#pragma unroll 4
        for (int k = 0; k < 128; k++) {
            float p = row[k] * inv;
            row[k] = p - m256;
            lss += p * p;
        }
        atomicAdd(&ssq[row_i & 7], lss);
    }
    __syncthreads();
    if (tid < 8) atomicAdd(&g_ssq[b * NH + tid], ssq[tid]);

    // ---- (P-m) @ V via 3-term bf16 m16n8k16 (non-amplified path) ----
    float accj[8][4];
#pragma unroll
    for (int jn = 0; jn < 8; jn++)
#pragma unroll
        for (int r = 0; r < 4; r++) accj[jn][r] = 0.f;

    for (int vc = 0; vc < 16; vc++) {
        if (vc + 1 < 16) {
            issue_rows(vp + (size_t)(vc + 1) * 16 * DD, (vc + 1) & 1);
            CP_COMMIT(); CP_WAIT1();
        } else CP_WAIT0();
        __syncthreads();
        const float* vt = kbuf + (vc & 1) * KB16;

        // A fragments: P rows gid and gid+8, k = vc*16 + {2tig,2tig+1,2tig+8,2tig+9}
        uint32_t ah[4], al[4];
        {
            const float* p0 = sc + (gid * 8 + h) * SC_STRIDE + vc * 16;
            const float* p8 = sc + ((gid + 8) * 8 + h) * SC_STRIDE + vc * 16;
            split_bf16x2(p0[2 * tig],     p0[2 * tig + 1], ah[0], al[0]);
            split_bf16x2(p8[2 * tig],     p8[2 * tig + 1], ah[1], al[1]);
            split_bf16x2(p0[2 * tig + 8], p0[2 * tig + 9], ah[2], al[2]);
            split_bf16x2(p8[2 * tig + 8], p8[2 * tig + 9], ah[3], al[3]);
        }

#pragma unroll
        for (int jn = 0; jn < 8; jn++) {
            uint32_t bh[2], bl[2];
            const float* vcol = vt + h * 64 + jn * 8 + gid;
            split_bf16x2(vcol[(2 * tig) * RW],     vcol[(2 * tig + 1) * RW], bh[0], bl[0]);
            split_bf16x2(vcol[(2 * tig + 8) * RW], vcol[(2 * tig + 9) * RW], bh[1], bl[1]);
            mma_bf16_k16(accj[jn], al, bh);
            mma_bf16_k16(accj[jn], ah, bl);
            mma_bf16_k16(accj[jn], ah, bh);
        }
        __syncthreads();
    }

    // epilogue: write (p-m)@V directly
#pragma unroll
    for (int jn = 0; jn < 8; jn++) {
        const int col = h * 64 + jn * 8 + tig * 2;
        float* o0 = g_ou + ((size_t)b * NQ + q0 + gid) * DD + col;
        float* o1 = g_ou + ((size_t)b * NQ + q0 + gid + 8) * DD + col;
        *(float2*)o0 = make_float2(accj[jn][0], accj[jn][1]);
        *(float2*)o1 = make_float2(accj[jn][2], accj[jn][3]);
    }
}

// ---------------------------------------------------------------------------
extern "C" void kernel_launch(void* const* d_in, const int* in_sizes, int n_in,
                              void* d_out, int out_size)
{
    (void)in_sizes; (void)n_in; (void)out_size;
    const float* queries = (const float*)d_in[0];
    const float* Wq = (const float*)d_in[1];
    const float* bq = (const float*)d_in[2];
    const float* Wk = (const float*)d_in[3];
    const float* bk = (const float*)d_in[4];
    const float* Wv = (const float*)d_in[5];
    const float* bv = (const float*)d_in[6];
    const float* Wo = (const float*)d_in[7];
    const float* bo = (const float*)d_in[8];
    const float* srw = (const float*)d_in[9];
    const float* srb = (const float*)d_in[10];
    const float* lng = (const float*)d_in[11];
    const float* lnb = (const float*)d_in[12];
    const float* tw  = (const float*)d_in[13];
    const float* tb  = (const float*)d_in[14];
    float* out = (float*)d_out;

    float *qp, *x, *kp, *vp, *ou, *wqt, *wkt, *wvt, *wot, *isp;
    cudaGetSymbolAddress((void**)&qp,  g_qp);
    cudaGetSymbolAddress((void**)&x,   g_x);
    cudaGetSymbolAddress((void**)&kp,  g_kp);
    cudaGetSymbolAddress((void**)&vp,  g_vp);
    cudaGetSymbolAddress((void**)&ou,  g_ou);
    cudaGetSymbolAddress((void**)&wqt, g_wqt);
    cudaGetSymbolAddress((void**)&wkt, g_wkt);
    cudaGetSymbolAddress((void**)&wvt, g_wvt);
    cudaGetSymbolAddress((void**)&wot, g_wot);
    cudaGetSymbolAddress((void**)&isp, g_is);

    const size_t attn_smem = ATT_SMEM_FLOATS * sizeof(float);
    cudaFuncSetAttribute(attn_kernel,
                         cudaFuncAttributeMaxDynamicSharedMemorySize,
                         (int)attn_smem);
    cudaFuncSetAttribute(gemm_mma,
                         cudaFuncAttributeMaxDynamicSharedMemorySize,
                         GM_SMEM);
    cudaFuncSetAttribute(gemm_bf16,
                         cudaFuncAttributeMaxDynamicSharedMemorySize,
                         GM_SMEM);

    zero_ssq_kernel<<<1, 128>>>();

    // transpose all 4 weights in one launch
    transpose4<<<dim3(16, 16, 4), dim3(32, 8)>>>(Wq, Wk, Wv, Wo,
                                                 wqt, wkt, wvt, wot);

    // Q projection (amplified path: 3xTF32)
    gemm_mma<<<dim3(4, 288), 256, GM_SMEM>>>(queries, wqt, bq, qp, BB * NQ, DD, DD);

    // spatial reduction conv + LN
    convln_kernel<<<dim3(256, 16), 256>>>(queries, srw, srb, lng, lnb);

    // K projection (amplified path: 3xTF32)
    gemm_mma<<<dim3(4, 32), 256, GM_SMEM>>>(x, wkt, bk, kp, BB * NKK, DD, DD);
    // V projection (safe path: bf16x3)
    gemm_bf16<<<dim3(4, 32), 256, GM_SMEM>>>(x, wvt, bv, vp, BB * NKK, DD, DD, nullptr);

    // fused attention (softmax stores p - 1/256; PV is non-amplified)
    attn_kernel<<<dim3(NQ / 16, BB), 256, attn_smem>>>(tw, tb);

    stats_kernel<<<1, 128>>>();

    // output projection with fused InstanceNorm scale (safe path: bf16x3)
    gemm_bf16<<<dim3(4, 288), 256, GM_SMEM>>>(ou, wot, bo, out, BB * NQ, DD, DD, isp);
}

// round 12
// speedup vs baseline: 2.3326x; 1.0318x over previous
#include <cuda_runtime.h>
#include <cuda_bf16.h>
#include <math.h>
#include <cstdint>

// Problem constants
#define BB   16
#define NQ   2304
#define DD   512
#define NH   8
#define DK   64
#define NKK  256
#define HHH  48

// Scratch (device globals; allocation-free per harness rules)
__device__ float g_qp[BB * NQ * DD];     // Q projection
__device__ float g_x [BB * NKK * DD];    // conv+LN output
__device__ float g_kp[BB * NKK * DD];    // K projection
__device__ float g_vp[BB * NKK * DD];    // V projection
__device__ float g_ou[BB * NQ * DD];     // (p-m) @ V
__device__ float g_ssq[BB * NH];         // sum of p^2 per (b,h)
__device__ float g_is [BB * NH];         // 1/sqrt(var+eps) per (b,h)
__device__ float g_wqt[DD * DD];         // transposed weights [N,K]
__device__ float g_wkt[DD * DD];
__device__ float g_wvt[DD * DD];
__device__ float g_wot[DD * DD];

__device__ __forceinline__ uint32_t f2tf32(float f) {
    uint32_t r;
    asm("cvt.rna.tf32.f32 %0, %1;" : "=r"(r) : "f"(f));
    return r;
}
__device__ __forceinline__ void split_tf32(float x, uint32_t& hi, uint32_t& lo) {
    hi = __float_as_uint(x) & 0xffffe000u;
    lo = f2tf32(x - __uint_as_float(hi));
}
__device__ __forceinline__ void split_bf16x2(float x0, float x1,
                                             uint32_t& hi, uint32_t& lo) {
    __nv_bfloat162 h = __floats2bfloat162_rn(x0, x1);
    float h0 = __bfloat162float(h.x);
    float h1 = __bfloat162float(h.y);
    __nv_bfloat162 l = __floats2bfloat162_rn(x0 - h0, x1 - h1);
    hi = *reinterpret_cast<uint32_t*>(&h);
    lo = *reinterpret_cast<uint32_t*>(&l);
}

__device__ __forceinline__ void mma_16n8k8(
    float* d, const uint32_t* a, const uint32_t* b)
{
    asm volatile(
        "mma.sync.aligned.m16n8k8.row.col.f32.tf32.tf32.f32 "
        "{%0,%1,%2,%3}, {%4,%5,%6,%7}, {%8,%9}, {%0,%1,%2,%3};"
        : "+f"(d[0]), "+f"(d[1]), "+f"(d[2]), "+f"(d[3])
        : "r"(a[0]), "r"(a[1]), "r"(a[2]), "r"(a[3]),
          "r"(b[0]), "r"(b[1]));
}
__device__ __forceinline__ void mma_bf16_k16(
    float* d, const uint32_t* a, const uint32_t* b)
{
    asm volatile(
        "mma.sync.aligned.m16n8k16.row.col.f32.bf16.bf16.f32 "
        "{%0,%1,%2,%3}, {%4,%5,%6,%7}, {%8,%9}, {%0,%1,%2,%3};"
        : "+f"(d[0]), "+f"(d[1]), "+f"(d[2]), "+f"(d[3])
        : "r"(a[0]), "r"(a[1]), "r"(a[2]), "r"(a[3]),
          "r"(b[0]), "r"(b[1]));
}

#define CP_A16(dst, src) \
    asm volatile("cp.async.cg.shared.global [%0], [%1], 16;" \
                 :: "r"(dst), "l"(src))
#define CP_COMMIT() asm volatile("cp.async.commit_group;" ::: "memory")
#define CP_WAIT1()  asm volatile("cp.async.wait_group 1;" ::: "memory")
#define CP_WAIT0()  asm volatile("cp.async.wait_group 0;" ::: "memory")

__device__ __forceinline__ uint32_t smem_u32(const void* p) {
    uint32_t a;
    asm("{ .reg .u64 t; cvta.to.shared.u64 t, %1; cvt.u32.u64 %0, t; }"
        : "=r"(a) : "l"(p));
    return a;
}

// ---------------------------------------------------------------------------
// Warp-MMA 3xTF32 GEMM (fp32 accuracy): C = A(MxK) @ Bt^T + bias.
// Used for Q and K projections (error-amplified paths).
// ---------------------------------------------------------------------------
#define GM_PAD 36
#define GM_BUF (128 * GM_PAD)
#define GM_SMEM (4 * GM_BUF * 4)

__global__ __launch_bounds__(256, 2) void gemm_mma(
    const float* __restrict__ A, const float* __restrict__ Bt,
    const float* __restrict__ bias, float* __restrict__ C,
    int M, int N, int K)
{
    extern __shared__ float gsm[];
    const int tid  = threadIdx.x;
    const int wid  = tid >> 5, lane = tid & 31;
    const int gid  = lane >> 2, tig = lane & 3;
    const int m_w  = (wid & 1) * 64;
    const int n_w  = (wid >> 1) * 32;
    const int m0   = blockIdx.y * 128;
    const int n0   = blockIdx.x * 128;

    const int lr = tid >> 1;
    const int lc = (tid & 1) * 16;
    const uint32_t sbase = smem_u32(gsm);

    float acc[4][4][4];
#pragma unroll
    for (int mi = 0; mi < 4; mi++)
#pragma unroll
        for (int ni = 0; ni < 4; ni++)
#pragma unroll
            for (int r = 0; r < 4; r++) acc[mi][ni][r] = 0.f;

    const int nch = K >> 5;

    auto issue = [&](int c, int buf) {
        const float* Ac = A  + (size_t)(m0 + lr) * K + c * 32 + lc;
        const float* Bc = Bt + (size_t)(n0 + lr) * K + c * 32 + lc;
        uint32_t da = sbase + (uint32_t)(buf * 2 * GM_BUF + lr * GM_PAD + lc) * 4;
        uint32_t db = da + GM_BUF * 4;
#pragma unroll
        for (int j = 0; j < 4; j++) {
            CP_A16(da + j * 16, Ac + j * 4);
            CP_A16(db + j * 16, Bc + j * 4);
        }
    };

    issue(0, 0);
    CP_COMMIT();

    for (int c = 0; c < nch; c++) {
        if (c + 1 < nch) {
            issue(c + 1, (c + 1) & 1);
            CP_COMMIT();
            CP_WAIT1();
        } else {
            CP_WAIT0();
        }
        __syncthreads();

        const float* As = gsm + (c & 1) * 2 * GM_BUF;
        const float* Bs = As + GM_BUF;

#pragma unroll
        for (int ks = 0; ks < 4; ks++) {
            const int kk = ks * 8;
            uint32_t bh[4][2], bl[4][2];
#pragma unroll
            for (int ni = 0; ni < 4; ni++) {
                int r = n_w + ni * 8 + gid;
                split_tf32(Bs[r * GM_PAD + kk + tig],     bh[ni][0], bl[ni][0]);
                split_tf32(Bs[r * GM_PAD + kk + tig + 4], bh[ni][1], bl[ni][1]);
            }
#pragma unroll
            for (int mi = 0; mi < 4; mi++) {
                uint32_t ah[4], al[4];
                int r0 = m_w + mi * 16 + gid;
                split_tf32(As[r0 * GM_PAD + kk + tig],           ah[0], al[0]);
                split_tf32(As[(r0 + 8) * GM_PAD + kk + tig],     ah[1], al[1]);
                split_tf32(As[r0 * GM_PAD + kk + tig + 4],       ah[2], al[2]);
                split_tf32(As[(r0 + 8) * GM_PAD + kk + tig + 4], ah[3], al[3]);
#pragma unroll
                for (int ni = 0; ni < 4; ni++) {
                    mma_16n8k8(acc[mi][ni], al, bh[ni]);
                    mma_16n8k8(acc[mi][ni], ah, bl[ni]);
                    mma_16n8k8(acc[mi][ni], ah, bh[ni]);
                }
            }
        }
        __syncthreads();
    }

#pragma unroll
    for (int mi = 0; mi < 4; mi++) {
        const int r0 = m0 + m_w + mi * 16 + gid;
        const int r1 = r0 + 8;
#pragma unroll
        for (int ni = 0; ni < 4; ni++) {
            const int col = n0 + n_w + ni * 8 + tig * 2;
            float2 bz = *(const float2*)&bias[col];
            float2 o0 = make_float2(acc[mi][ni][0] + bz.x, acc[mi][ni][1] + bz.y);
            float2 o1 = make_float2(acc[mi][ni][2] + bz.x, acc[mi][ni][3] + bz.y);
            *(float2*)&C[(size_t)r0 * N + col] = o0;
            *(float2*)&C[(size_t)r1 * N + col] = o1;
        }
    }
}

// ---------------------------------------------------------------------------
// Warp-MMA 3-term bf16 GEMM: C = (A*colscale)(MxK) @ Bt^T + bias.
// Used for V projection (is_all=null) and output projection (is_all=g_is).
// ---------------------------------------------------------------------------
__global__ __launch_bounds__(256, 2) void gemm_bf16(
    const float* __restrict__ A, const float* __restrict__ Bt,
    const float* __restrict__ bias, float* __restrict__ C,
    int M, int N, int K, const float* __restrict__ is_all)
{
    extern __shared__ float gsm[];
    const int tid  = threadIdx.x;
    const int wid  = tid >> 5, lane = tid & 31;
    const int gid  = lane >> 2, tig = lane & 3;
    const int m_w  = (wid & 1) * 64;
    const int n_w  = (wid >> 1) * 32;
    const int m0   = blockIdx.y * 128;
    const int n0   = blockIdx.x * 128;

    const int lr = tid >> 1;
    const int lc = (tid & 1) * 16;
    const uint32_t sbase = smem_u32(gsm);

    float acc[4][4][4];
#pragma unroll
    for (int mi = 0; mi < 4; mi++)
#pragma unroll
        for (int ni = 0; ni < 4; ni++)
#pragma unroll
            for (int r = 0; r < 4; r++) acc[mi][ni][r] = 0.f;

    const int nch = K >> 5;

    auto issue = [&](int c, int buf) {
        const float* Ac = A  + (size_t)(m0 + lr) * K + c * 32 + lc;
        const float* Bc = Bt + (size_t)(n0 + lr) * K + c * 32 + lc;
        uint32_t da = sbase + (uint32_t)(buf * 2 * GM_BUF + lr * GM_PAD + lc) * 4;
        uint32_t db = da + GM_BUF * 4;
#pragma unroll
        for (int j = 0; j < 4; j++) {
            CP_A16(da + j * 16, Ac + j * 4);
            CP_A16(db + j * 16, Bc + j * 4);
        }
    };

    issue(0, 0);
    CP_COMMIT();

    for (int c = 0; c < nch; c++) {
        if (c + 1 < nch) {
            issue(c + 1, (c + 1) & 1);
            CP_COMMIT();
            CP_WAIT1();
        } else {
            CP_WAIT0();
        }
        __syncthreads();

        const float* As = gsm + (c & 1) * 2 * GM_BUF;
        const float* Bs = As + GM_BUF;

        // per-chunk uniform InstanceNorm scale: head index = c>>1
        float s_cur = 1.f;
        if (is_all) s_cur = is_all[(m0 / NQ) * NH + (c >> 1)];

#pragma unroll
        for (int ks = 0; ks < 2; ks++) {
            const int kb = ks * 16;
            uint32_t bh[4][2], bl[4][2];
#pragma unroll
            for (int ni = 0; ni < 4; ni++) {
                int r = n_w + ni * 8 + gid;
                float2 v0 = *(const float2*)&Bs[r * GM_PAD + kb + 2 * tig];
                float2 v1 = *(const float2*)&Bs[r * GM_PAD + kb + 2 * tig + 8];
                split_bf16x2(v0.x, v0.y, bh[ni][0], bl[ni][0]);
                split_bf16x2(v1.x, v1.y, bh[ni][1], bl[ni][1]);
            }
#pragma unroll
            for (int mi = 0; mi < 4; mi++) {
                uint32_t ah[4], al[4];
                int r0 = m_w + mi * 16 + gid;
                float2 a0 = *(const float2*)&As[r0 * GM_PAD + kb + 2 * tig];
                float2 a1 = *(const float2*)&As[(r0 + 8) * GM_PAD + kb + 2 * tig];
                float2 a2 = *(const float2*)&As[r0 * GM_PAD + kb + 2 * tig + 8];
                float2 a3 = *(const float2*)&As[(r0 + 8) * GM_PAD + kb + 2 * tig + 8];
                split_bf16x2(a0.x * s_cur, a0.y * s_cur, ah[0], al[0]);
                split_bf16x2(a1.x * s_cur, a1.y * s_cur, ah[1], al[1]);
                split_bf16x2(a2.x * s_cur, a2.y * s_cur, ah[2], al[2]);
                split_bf16x2(a3.x * s_cur, a3.y * s_cur, ah[3], al[3]);
#pragma unroll
                for (int ni = 0; ni < 4; ni++) {
                    mma_bf16_k16(acc[mi][ni], al, bh[ni]);
                    mma_bf16_k16(acc[mi][ni], ah, bl[ni]);
                    mma_bf16_k16(acc[mi][ni], ah, bh[ni]);
                }
            }
        }
        __syncthreads();
    }

#pragma unroll
    for (int mi = 0; mi < 4; mi++) {
        const int r0 = m0 + m_w + mi * 16 + gid;
        const int r1 = r0 + 8;
#pragma unroll
        for (int ni = 0; ni < 4; ni++) {
            const int col = n0 + n_w + ni * 8 + tig * 2;
            float2 bz = *(const float2*)&bias[col];
            float2 o0 = make_float2(acc[mi][ni][0] + bz.x, acc[mi][ni][1] + bz.y);
            float2 o1 = make_float2(acc[mi][ni][2] + bz.x, acc[mi][ni][3] + bz.y);
            *(float2*)&C[(size_t)r0 * N + col] = o0;
            *(float2*)&C[(size_t)r1 * N + col] = o1;
        }
    }
}

// ---------------------------------------------------------------------------
// 4x 512x512 transpose in one launch: Wt[n,k] = W[k,n]
// ---------------------------------------------------------------------------
__global__ void transpose4(
    const float* __restrict__ W0, const float* __restrict__ W1,
    const float* __restrict__ W2, const float* __restrict__ W3,
    float* __restrict__ T0, float* __restrict__ T1,
    float* __restrict__ T2, float* __restrict__ T3)
{
    const float* W; float* T;
    switch (blockIdx.z) {
        case 0: W = W0; T = T0; break;
        case 1: W = W1; T = T1; break;
        case 2: W = W2; T = T2; break;
        default: W = W3; T = T3; break;
    }
    __shared__ float t[32][33];
    const int bx = blockIdx.x * 32, by = blockIdx.y * 32;
    const int tx = threadIdx.x, ty = threadIdx.y;   // 32 x 8
#pragma unroll
    for (int i = 0; i < 32; i += 8)
        t[ty + i][tx] = W[(size_t)(by + ty + i) * DD + bx + tx];
    __syncthreads();
#pragma unroll
    for (int i = 0; i < 32; i += 8)
        T[(size_t)(bx + ty + i) * DD + by + tx] = t[tx][ty + i];
}

// ---------------------------------------------------------------------------
// Depthwise 4x4 stride-3 conv (pad 1) + LayerNorm over channels.
// ---------------------------------------------------------------------------
__global__ __launch_bounds__(256) void convln_kernel(
    const float* __restrict__ q, const float* __restrict__ srw,
    const float* __restrict__ srb, const float* __restrict__ lng,
    const float* __restrict__ lnb)
{
    const int b  = blockIdx.y;
    const int op = blockIdx.x;
    const int oh = op >> 4, ow = op & 15;
    const int tid = threadIdx.x;
    const int c0 = tid, c1 = tid + 256;

    float a0 = srb[c0], a1 = srb[c1];
#pragma unroll
    for (int kh = 0; kh < 4; kh++) {
        int ih = oh * 3 - 1 + kh;
        if (ih < 0 || ih >= HHH) continue;
#pragma unroll
        for (int kw = 0; kw < 4; kw++) {
            int iw = ow * 3 - 1 + kw;
            if (iw < 0 || iw >= HHH) continue;
            const float* qr = q + ((size_t)b * NQ + ih * HHH + iw) * DD;
            a0 += srw[c0 * 16 + kh * 4 + kw] * qr[c0];
            a1 += srw[c1 * 16 + kh * 4 + kw] * qr[c1];
        }
    }

    float s  = a0 + a1;
    float s2 = a0 * a0 + a1 * a1;
#pragma unroll
    for (int off = 16; off; off >>= 1) {
        s  += __shfl_xor_sync(0xFFFFFFFFu, s,  off);
        s2 += __shfl_xor_sync(0xFFFFFFFFu, s2, off);
    }
    __shared__ float rs[8], rs2[8];
    if ((tid & 31) == 0) { rs[tid >> 5] = s; rs2[tid >> 5] = s2; }
    __syncthreads();
    if (tid == 0) {
        float ts = 0.f, ts2 = 0.f;
#pragma unroll
        for (int i = 0; i < 8; i++) { ts += rs[i]; ts2 += rs2[i]; }
        rs[0] = ts; rs2[0] = ts2;
    }
    __syncthreads();
    const float mu   = rs[0] * (1.f / 512.f);
    const float var  = rs2[0] * (1.f / 512.f) - mu * mu;
    const float rstd = rsqrtf(var + 1e-5f);

    float* xo = g_x + ((size_t)b * NKK + op) * DD;
    xo[c0] = (a0 - mu) * rstd * lng[c0] + lnb[c0];
    xo[c1] = (a1 - mu) * rstd * lng[c1] + lnb[c1];
}

__global__ void zero_ssq_kernel()
{
    if (threadIdx.x < BB * NH) g_ssq[threadIdx.x] = 0.f;
}

__global__ void stats_kernel()
{
    const int i = threadIdx.x;
    if (i < BB * NH) {
        const float m = 1.f / 256.f;
        float va = g_ssq[i] / (2304.f * 256.f) - m * m;
        g_is[i] = rsqrtf(va + 1e-5f);
    }
}

// ---------------------------------------------------------------------------
// Fused attention v6: 3-term bf16 m16n8k16 for BOTH QK and PV.
// (p-m) stored by softmax; PV non-amplified.
// Block = (b, 16-query tile), 256 threads, warp = head.
// smem: sc[128][257], kbuf 2 x [16][516] (Q staged in buf1), consts.
// ---------------------------------------------------------------------------
#define SC_STRIDE 257
#define RW 516
#define KB16 (16 * RW)
#define ATT_SMEM_FLOATS (128 * SC_STRIDE + 2 * KB16 + 64 + 8 + 8)

__global__ __launch_bounds__(256, 1) void attn_kernel(
    const float* __restrict__ tw, const float* __restrict__ tb)
{
    extern __shared__ float sm[];
    float* sc   = sm;                        // 128 * 257
    float* kbuf = sc + 128 * SC_STRIDE;      // 2 * 16 * 516
    float* tws  = kbuf + 2 * KB16;           // 64
    float* tbs  = tws + 64;                  // 8
    float* ssq  = tbs + 8;                   // 8

    const int tid  = threadIdx.x;
    const int h    = tid >> 5;               // warp = head
    const int lane = tid & 31;
    const int gid  = lane >> 2, tig = lane & 3;
    const int b    = blockIdx.y;
    const int q0   = blockIdx.x * 16;
    const uint32_t kb_addr = smem_u32(kbuf);

    if (tid < 64) tws[tid] = tw[tid];
    if (tid < 8) { tbs[tid] = tb[tid]; ssq[tid] = 0.f; }

    const float* kp = g_kp + (size_t)b * NKK * DD;
    const float* vp = g_vp + (size_t)b * NKK * DD;
    const float* qp = g_qp + ((size_t)b * NQ + q0) * DD;

    // cp.async one 16-row x 512 chunk into buffer `buf`
    auto issue_rows = [&](const float* src, int buf) {
        uint32_t dst = kb_addr + (uint32_t)(buf * KB16) * 4;
#pragma unroll
        for (int it = 0; it < 8; it++) {
            int idx = tid + it * 256;
            int r = idx >> 7, c4 = (idx & 127) << 2;
            CP_A16(dst + (uint32_t)(r * RW + c4) * 4, src + (size_t)r * DD + c4);
        }
    };

    // stage Q into buf1 and K chunk 0 into buf0 concurrently
    issue_rows(qp, 1);
    issue_rows(kp, 0);
    CP_COMMIT();
    CP_WAIT0();
    __syncthreads();

    // Q fragments for this head (k16 layout), split hi/lo, held in registers
    uint32_t qh[4][4], ql[4][4];
    {
        const float* qsb = kbuf + KB16;
#pragma unroll
        for (int ks = 0; ks < 4; ks++) {
            const float* qb = qsb + h * 64 + ks * 16;
            split_bf16x2(qb[gid * RW + 2 * tig],
                         qb[gid * RW + 2 * tig + 1],       qh[ks][0], ql[ks][0]);
            split_bf16x2(qb[(gid + 8) * RW + 2 * tig],
                         qb[(gid + 8) * RW + 2 * tig + 1], qh[ks][1], ql[ks][1]);
            split_bf16x2(qb[gid * RW + 2 * tig + 8],
                         qb[gid * RW + 2 * tig + 9],       qh[ks][2], ql[ks][2]);
            split_bf16x2(qb[(gid + 8) * RW + 2 * tig + 8],
                         qb[(gid + 8) * RW + 2 * tig + 9], qh[ks][3], ql[ks][3]);
        }
    }
    __syncthreads();

    // ---- QK: S[q][k] for this head, 16 keys per chunk (bf16x3 k16) ----
    for (int kc = 0; kc < 16; kc++) {
        if (kc + 1 < 16) {
            issue_rows(kp + (size_t)(kc + 1) * 16 * DD, (kc + 1) & 1);
            CP_COMMIT(); CP_WAIT1();
        } else CP_WAIT0();
        __syncthreads();
        const float* kt = kbuf + (kc & 1) * KB16;

#pragma unroll
        for (int ni = 0; ni < 2; ni++) {
            float acc[4] = {0.f, 0.f, 0.f, 0.f};
#pragma unroll
            for (int ks = 0; ks < 4; ks++) {
                uint32_t bh[2], bl[2];
                const float* kr = kt + (ni * 8 + gid) * RW + h * 64 + ks * 16;
                split_bf16x2(kr[2 * tig],     kr[2 * tig + 1], bh[0], bl[0]);
                split_bf16x2(kr[2 * tig + 8], kr[2 * tig + 9], bh[1], bl[1]);
                mma_bf16_k16(acc, ql[ks], bh);
                mma_bf16_k16(acc, qh[ks], bl);
                mma_bf16_k16(acc, qh[ks], bh);
            }
            const int kbcol = kc * 16 + ni * 8 + tig * 2;
            float* r0 = sc + (gid * 8 + h) * SC_STRIDE + kbcol;
            float* r1 = sc + ((gid + 8) * 8 + h) * SC_STRIDE + kbcol;
            r0[0] = acc[0] * 0.125f; r0[1] = acc[1] * 0.125f;
            r1[0] = acc[2] * 0.125f; r1[1] = acc[3] * 0.125f;
        }
        __syncthreads();
    }

    // prefetch V chunk 0 (overlaps headmix + softmax)
    issue_rows(vp, 0);
    CP_COMMIT();

    // ---- head mixing: s2[o][k] = tb[o] + sum_i tw[o][i]*s[i][k] ----
    {
        const int k = tid;  // 0..255
        for (int q = 0; q < 16; q++) {
            float r[8];
#pragma unroll
            for (int i = 0; i < 8; i++) r[i] = sc[(q * 8 + i) * SC_STRIDE + k];
            float o_[8];
#pragma unroll
            for (int o = 0; o < 8; o++) {
                float s = tbs[o];
#pragma unroll
                for (int i = 0; i < 8; i++) s += tws[o * 8 + i] * r[i];
                o_[o] = s;
            }
#pragma unroll
            for (int o = 0; o < 8; o++) sc[(q * 8 + o) * SC_STRIDE + k] = o_[o];
        }
    }
    __syncthreads();

    // ---- softmax per (q,o) row: all 256 threads, 2 per row ----
    // writes (p - 1/256) back; accumulates sum p^2
    {
        const float m256 = 1.f / 256.f;
        const int row_i = tid >> 1;          // 0..127
        const int half  = tid & 1;
        float* row = sc + row_i * SC_STRIDE + half * 128;
        float mx = -1e30f;
#pragma unroll 4
        for (int k = 0; k < 128; k++) mx = fmaxf(mx, row[k]);
        mx = fmaxf(mx, __shfl_xor_sync(0xFFFFFFFFu, mx, 1));
        float s = 0.f;
#pragma unroll 4
        for (int k = 0; k < 128; k++) { float e = expf(row[k] - mx); row[k] = e; s += e; }
        s += __shfl_xor_sync(0xFFFFFFFFu, s, 1);
        float inv = 1.f / s;
        float lss = 0.f;
#pragma unroll 4
        for (int k = 0; k < 128; k++) {
            float p = row[k] * inv;
            row[k] = p - m256;
            lss += p * p;
        }
        atomicAdd(&ssq[row_i & 7], lss);
    }
    __syncthreads();
    if (tid < 8) atomicAdd(&g_ssq[b * NH + tid], ssq[tid]);

    // ---- (P-m) @ V via 3-term bf16 m16n8k16 (non-amplified path) ----
    float accj[8][4];
#pragma unroll
    for (int jn = 0; jn < 8; jn++)
#pragma unroll
        for (int r = 0; r < 4; r++) accj[jn][r] = 0.f;

    for (int vc = 0; vc < 16; vc++) {
        if (vc + 1 < 16) {
            issue_rows(vp + (size_t)(vc + 1) * 16 * DD, (vc + 1) & 1);
            CP_COMMIT(); CP_WAIT1();
        } else CP_WAIT0();
        __syncthreads();
        const float* vt = kbuf + (vc & 1) * KB16;

        // A fragments: P rows gid and gid+8, k = vc*16 + {2tig,2tig+1,2tig+8,2tig+9}
        uint32_t ah[4], al[4];
        {
            const float* p0 = sc + (gid * 8 + h) * SC_STRIDE + vc * 16;
            const float* p8 = sc + ((gid + 8) * 8 + h) * SC_STRIDE + vc * 16;
            split_bf16x2(p0[2 * tig],     p0[2 * tig + 1], ah[0], al[0]);
            split_bf16x2(p8[2 * tig],     p8[2 * tig + 1], ah[1], al[1]);
            split_bf16x2(p0[2 * tig + 8], p0[2 * tig + 9], ah[2], al[2]);
            split_bf16x2(p8[2 * tig + 8], p8[2 * tig + 9], ah[3], al[3]);
        }

#pragma unroll
        for (int jn = 0; jn < 8; jn++) {
            uint32_t bh[2], bl[2];
            const float* vcol = vt + h * 64 + jn * 8 + gid;
            split_bf16x2(vcol[(2 * tig) * RW],     vcol[(2 * tig + 1) * RW], bh[0], bl[0]);
            split_bf16x2(vcol[(2 * tig + 8) * RW], vcol[(2 * tig + 9) * RW], bh[1], bl[1]);
            mma_bf16_k16(accj[jn], al, bh);
            mma_bf16_k16(accj[jn], ah, bl);
            mma_bf16_k16(accj[jn], ah, bh);
        }
        __syncthreads();
    }

    // epilogue: write (p-m)@V directly
#pragma unroll
    for (int jn = 0; jn < 8; jn++) {
        const int col = h * 64 + jn * 8 + tig * 2;
        float* o0 = g_ou + ((size_t)b * NQ + q0 + gid) * DD + col;
        float* o1 = g_ou + ((size_t)b * NQ + q0 + gid + 8) * DD + col;
        *(float2*)o0 = make_float2(accj[jn][0], accj[jn][1]);
        *(float2*)o1 = make_float2(accj[jn][2], accj[jn][3]);
    }
}

// ---------------------------------------------------------------------------
extern "C" void kernel_launch(void* const* d_in, const int* in_sizes, int n_in,
                              void* d_out, int out_size)
{
    (void)in_sizes; (void)n_in; (void)out_size;
    const float* queries = (const float*)d_in[0];
    const float* Wq = (const float*)d_in[1];
    const float* bq = (const float*)d_in[2];
    const float* Wk = (const float*)d_in[3];
    const float* bk = (const float*)d_in[4];
    const float* Wv = (const float*)d_in[5];
    const float* bv = (const float*)d_in[6];
    const float* Wo = (const float*)d_in[7];
    const float* bo = (const float*)d_in[8];
    const float* srw = (const float*)d_in[9];
    const float* srb = (const float*)d_in[10];
    const float* lng = (const float*)d_in[11];
    const float* lnb = (const float*)d_in[12];
    const float* tw  = (const float*)d_in[13];
    const float* tb  = (const float*)d_in[14];
    float* out = (float*)d_out;

    float *qp, *x, *kp, *vp, *ou, *wqt, *wkt, *wvt, *wot, *isp;
    cudaGetSymbolAddress((void**)&qp,  g_qp);
    cudaGetSymbolAddress((void**)&x,   g_x);
    cudaGetSymbolAddress((void**)&kp,  g_kp);
    cudaGetSymbolAddress((void**)&vp,  g_vp);
    cudaGetSymbolAddress((void**)&ou,  g_ou);
    cudaGetSymbolAddress((void**)&wqt, g_wqt);
    cudaGetSymbolAddress((void**)&wkt, g_wkt);
    cudaGetSymbolAddress((void**)&wvt, g_wvt);
    cudaGetSymbolAddress((void**)&wot, g_wot);
    cudaGetSymbolAddress((void**)&isp, g_is);

    const size_t attn_smem = ATT_SMEM_FLOATS * sizeof(float);
    cudaFuncSetAttribute(attn_kernel,
                         cudaFuncAttributeMaxDynamicSharedMemorySize,
                         (int)attn_smem);
    cudaFuncSetAttribute(gemm_mma,
                         cudaFuncAttributeMaxDynamicSharedMemorySize,
                         GM_SMEM);
    cudaFuncSetAttribute(gemm_bf16,
                         cudaFuncAttributeMaxDynamicSharedMemorySize,
                         GM_SMEM);

    zero_ssq_kernel<<<1, 128>>>();

    // transpose all 4 weights in one launch
    transpose4<<<dim3(16, 16, 4), dim3(32, 8)>>>(Wq, Wk, Wv, Wo,
                                                 wqt, wkt, wvt, wot);

    // Q projection (amplified path: 3xTF32)
    gemm_mma<<<dim3(4, 288), 256, GM_SMEM>>>(queries, wqt, bq, qp, BB * NQ, DD, DD);

    // spatial reduction conv + LN
    convln_kernel<<<dim3(256, 16), 256>>>(queries, srw, srb, lng, lnb);

    // K projection (amplified path: 3xTF32)
    gemm_mma<<<dim3(4, 32), 256, GM_SMEM>>>(x, wkt, bk, kp, BB * NKK, DD, DD);
    // V projection (safe path: bf16x3)
    gemm_bf16<<<dim3(4, 32), 256, GM_SMEM>>>(x, wvt, bv, vp, BB * NKK, DD, DD, nullptr);

    // fused attention (softmax stores p - 1/256; PV is non-amplified)
    attn_kernel<<<dim3(NQ / 16, BB), 256, attn_smem>>>(tw, tb);

    stats_kernel<<<1, 128>>>();

    // output projection with fused InstanceNorm scale (safe path: bf16x3)
    gemm_bf16<<<dim3(4, 288), 256, GM_SMEM>>>(ou, wot, bo, out, BB * NQ, DD, DD, isp);
}